// round 1
// baseline (speedup 1.0000x reference)
#include <cuda_runtime.h>
#include <math.h>

#define EPSF 1e-8f
#define NB 3
#define NF 1024
#define NP 768
#define IMG 128
#define TPX 8          // 8x8 pixel tiles
#define TILES_X 16
#define NTILE 256      // 16x16 tiles
#define LIST_STRIDE (NF + 1)

// out offsets (f32 elements)
#define OFF_IM     0
#define OFF_PROB   49152
#define OFF_NORM   65536
#define OFF_FG     74752

__constant__ float c_unused[1]; // keep nvcc happy if unused sections stripped

static __device__ __align__(16) float g_face[NB * NF * 16];
static __device__ int g_list[NB * NTILE * LIST_STRIDE];

__device__ __forceinline__ float pix_x(int x) {
    const float STEP = 2.0f / 127.0f;
    return (x == 127) ? 1.0f : (-1.0f + x * STEP);
}
__device__ __forceinline__ float pix_y(int y) {
    const float STEP = 2.0f / 127.0f;
    return (y == 127) ? -1.0f : (1.0f - y * STEP);
}

// ---------------------------------------------------------------------------
// Kernel 1: per (batch, face) precompute.
// Transforms vertices, computes screen coords, edge coefficients, denom, bbox,
// and writes the unit normal directly to the output's normals section.
// ---------------------------------------------------------------------------
__global__ void prep_kernel(const float* __restrict__ pts,
                            const float* __restrict__ camrot,
                            const float* __restrict__ campos,
                            const float* __restrict__ proj,
                            const int*   __restrict__ faces,
                            float* __restrict__ out_normals) {
    int gid = blockIdx.x * blockDim.x + threadIdx.x;
    if (gid >= NB * NF) return;
    int l = gid / NF, f = gid % NF;

    int vi0 = faces[f * 3 + 0];
    int vi1 = faces[f * 3 + 1];
    int vi2 = faces[f * 3 + 2];
    int vis[3] = {vi0, vi1, vi2};

    const float* R = camrot + l * 9;
    const float* C = campos + l * 3;
    float p0 = proj[0], p1 = proj[1];

    float vx[3], vy[3], vz[3], sx[3], sy[3];
#pragma unroll
    for (int k = 0; k < 3; k++) {
        const float* P = pts + (l * NP + vis[k]) * 3;
        float q0 = P[0] - C[0], q1 = P[1] - C[1], q2 = P[2] - C[2];
        float X = R[0] * q0 + R[1] * q1 + R[2] * q2;
        float Y = R[3] * q0 + R[4] * q1 + R[5] * q2;
        float Z = R[6] * q0 + R[7] * q1 + R[8] * q2;
        vx[k] = X; vy[k] = Y; vz[k] = Z;
        float zd = Z + EPSF;
        sx[k] = __fdiv_rn(X * p0, zd);
        sy[k] = __fdiv_rn(Y * p1, zd);
    }

    // face normal (matches jnp.cross(v1-v0, v2-v0), normalized)
    float e1x = vx[1] - vx[0], e1y = vy[1] - vy[0], e1z = vz[1] - vz[0];
    float e2x = vx[2] - vx[0], e2y = vy[2] - vy[0], e2z = vz[2] - vz[0];
    float nx = e1y * e2z - e1z * e2y;
    float ny = e1z * e2x - e1x * e2z;
    float nz = e1x * e2y - e1y * e2x;
    float nn = __fsqrt_rn(nx * nx + ny * ny + nz * nz) + EPSF;
    out_normals[gid * 3 + 0] = __fdiv_rn(nx, nn);
    out_normals[gid * 3 + 1] = __fdiv_rn(ny, nn);
    out_normals[gid * 3 + 2] = __fdiv_rn(nz, nn);

    float ax = sx[0], ay = sy[0], bx = sx[1], by = sy[1], cx = sx[2], cy = sy[2];
    float d = (by - cy) * (ax - cx) + (cx - bx) * (ay - cy);
    float zmax = fmaxf(vz[0], fmaxf(vz[1], vz[2]));
    bool valid = (fabsf(d) > EPSF) && (zmax > EPSF);

    const float STEP = 2.0f / 127.0f;
    float pad = 2.0f * STEP;   // 2px safety pad against FP edge noise
    float xmin, xmax, ymin, ymax;
    if (valid) {
        xmin = fminf(ax, fminf(bx, cx)) - pad;
        xmax = fmaxf(ax, fmaxf(bx, cx)) + pad;
        ymin = fminf(ay, fminf(by, cy)) - pad;
        ymax = fmaxf(ay, fmaxf(by, cy)) + pad;
    } else {
        xmin = 3e38f; xmax = -3e38f; ymin = 3e38f; ymax = -3e38f;
    }

    float* F = g_face + gid * 16;
    F[0]  = by - cy;        // e0x
    F[1]  = cx - bx;        // e0y
    F[2]  = cy - ay;        // e1x
    F[3]  = ax - cx;        // e1y
    F[4]  = cx;
    F[5]  = cy;
    F[6]  = d + EPSF;       // denom
    F[7]  = vz[0];
    F[8]  = vz[1];
    F[9]  = vz[2];
    F[10] = 0.0f;
    F[11] = 0.0f;
    F[12] = xmin;
    F[13] = xmax;
    F[14] = ymin;
    F[15] = ymax;
}

// ---------------------------------------------------------------------------
// Kernel 2: per (batch, tile) ordered face-list compaction (1 warp each).
// Ballot + popc scan preserves ascending face order -> argmin tie semantics.
// ---------------------------------------------------------------------------
__global__ void build_kernel() {
    int bid = blockIdx.x;           // 0 .. NB*NTILE-1
    int l = bid / NTILE, t = bid % NTILE;
    int tx0 = (t & (TILES_X - 1)) * TPX;
    int ty0 = (t / TILES_X) * TPX;
    float xlo = pix_x(tx0),            xhi = pix_x(tx0 + TPX - 1);
    float yhi = pix_y(ty0),            ylo = pix_y(ty0 + TPX - 1);

    int lane = threadIdx.x;
    int* list = g_list + (l * NTILE + t) * LIST_STRIDE;
    int count = 0;
    for (int base = 0; base < NF; base += 32) {
        int f = base + lane;
        const float4 bb = *reinterpret_cast<const float4*>(g_face + (l * NF + f) * 16 + 12);
        bool pred = (bb.x <= xhi) && (bb.y >= xlo) && (bb.z <= yhi) && (bb.w >= ylo);
        unsigned m = __ballot_sync(0xffffffffu, pred);
        if (pred)
            list[1 + count + __popc(m & ((1u << lane) - 1u))] = f;
        count += __popc(m);
    }
    if (lane == 0) list[0] = count;
}

// ---------------------------------------------------------------------------
// Kernel 3: raster + composite + fragment shader. One block per 8x8 tile,
// one thread per pixel; all 3 batch layers handled in-block so compositing
// and texture sampling happen once per pixel.
// ---------------------------------------------------------------------------
__global__ void __launch_bounds__(64)
raster_kernel(const float* __restrict__ ts,
              const int*   __restrict__ faces,
              const float* __restrict__ uv,
              const float* __restrict__ tex,
              float* __restrict__ out) {
    int t = blockIdx.x;
    int x = ((t & (TILES_X - 1)) << 3) + (threadIdx.x & 7);
    int y = ((t / TILES_X) << 3) + (threadIdx.x >> 3);
    float px = pix_x(x), py = pix_y(y);

    float a0s[3], a1s[3];
    int   fis[3];
    bool  hs[3];

#pragma unroll
    for (int l = 0; l < 3; l++) {
        const int* list = g_list + (l * NTILE + t) * LIST_STRIDE;
        int n = list[0];
        const float* fbase = g_face + l * NF * 16;
        float best = 1e10f;
        int fi = 0;
        float a0 = 0.0f, a1 = 0.0f;
        bool h = false;
        for (int j = 0; j < n; j++) {
            int f = list[1 + j];
            const float* fd = fbase + f * 16;
            float4 bb = *reinterpret_cast<const float4*>(fd + 12);
            if (px < bb.x || px > bb.y || py < bb.z || py > bb.w) continue;
            float4 A = *reinterpret_cast<const float4*>(fd);      // e0x,e0y,e1x,e1y
            float4 B = *reinterpret_cast<const float4*>(fd + 4);  // cx,cy,denom,z0
            float z1v = fd[8], z2v = fd[9];
            float dx = px - B.x, dy = py - B.y;
            float l0 = __fdiv_rn(A.x * dx + A.y * dy, B.z);
            float l1 = __fdiv_rn(A.z * dx + A.w * dy, B.z);
            float l2 = 1.0f - l0 - l1;
            float z = l0 * B.w + l1 * z1v + l2 * z2v;
            if (l0 >= 0.0f && l1 >= 0.0f && l2 >= 0.0f && z > EPSF && z < best) {
                best = z; fi = f; a0 = l0; a1 = l1; h = true;
            }
        }
        a0s[l] = a0; a1s[l] = a1; fis[l] = fi; hs[l] = h;
    }

    // stable argsort of -ts[:,2] over 3 layers (matches jnp.argsort stability)
    float k0 = -ts[2], k1 = -ts[5], k2 = -ts[8];
    int o0 = 0; float kv = k0;
    if (k1 < kv) { o0 = 1; kv = k1; }
    if (k2 < kv) { o0 = 2; kv = k2; }
    int r0 = (o0 == 0) ? 1 : 0;
    int r1 = (o0 == 2) ? 1 : 2;
    float kr0 = (r0 == 0) ? k0 : k1;
    float kr1 = (r1 == 1) ? k1 : k2;
    int o1, o2;
    if (kr0 <= kr1) { o1 = r0; o2 = r1; }
    else            { o1 = r1; o2 = r0; }

    // composite: start with front-sorted layer, later layers overwrite if masked
    int sel = o0;
    if (hs[o1]) sel = o1;
    if (hs[o2]) sel = o2;

    float c0 = 0.0f, c1 = 0.0f, c2 = 0.0f, hard = 0.0f;
    if (hs[sel]) {
        hard = 1.0f;
        int f = fis[sel];
        int i0 = faces[f * 3 + 0];
        int i1 = faces[f * 3 + 1];
        int i2 = faces[f * 3 + 2];
        const float* U = uv + sel * NP * 2;
        float l0 = a0s[sel], l1 = a1s[sel], l2 = 1.0f - l0 - l1;
        float u = l0 * U[2 * i0]     + l1 * U[2 * i1]     + l2 * U[2 * i2];
        float v = l0 * U[2 * i0 + 1] + l1 * U[2 * i1 + 1] + l2 * U[2 * i2 + 1];
        u = fminf(fmaxf(u, 0.0f), 1.0f);
        v = fminf(fmaxf(v, 0.0f), 1.0f);
        int txi = (int)rintf(u * 511.0f);               // round-half-even = numpy
        int tyi = (int)rintf((1.0f - v) * 511.0f);
        const float* T = tex + sel * 3 * 512 * 512 + tyi * 512 + txi;
        c0 = T[0];
        c1 = T[262144];
        c2 = T[524288];
    }

    int pid = y * IMG + x;
    out[OFF_IM + pid * 3 + 0] = c0;
    out[OFF_IM + pid * 3 + 1] = c1;
    out[OFF_IM + pid * 3 + 2] = c2;
    out[OFF_PROB + pid] = hard;
    out[OFF_FG + pid]   = hard;
}

// ---------------------------------------------------------------------------
extern "C" void kernel_launch(void* const* d_in, const int* in_sizes, int n_in,
                              void* d_out, int out_size) {
    const float* points = (const float*)d_in[0];
    const float* camrot = (const float*)d_in[1];
    const float* campos = (const float*)d_in[2];
    const float* proj   = (const float*)d_in[3];
    const float* uv     = (const float*)d_in[4];
    const float* tex    = (const float*)d_in[5];
    const float* ts     = (const float*)d_in[6];
    const int*   faces  = (const int*)d_in[7];
    float* out = (float*)d_out;

    prep_kernel<<<(NB * NF + 255) / 256, 256>>>(points, camrot, campos, proj,
                                                faces, out + OFF_NORM);
    build_kernel<<<NB * NTILE, 32>>>();
    raster_kernel<<<NTILE, 64>>>(ts, faces, uv, tex, out);
}

// round 2
// speedup vs baseline: 5.9531x; 5.9531x over previous
#include <cuda_runtime.h>
#include <math.h>

#define EPSF 1e-8f
#define NB 3
#define NF 1024
#define NP 768
#define IMG 128
#define TPX 8          // 8x8 pixel tiles
#define TILES_X 16
#define NTILE 256      // 16x16 tiles
#define LIST_STRIDE (NF + 1)

// out offsets (f32 elements)
#define OFF_IM     0
#define OFF_PROB   49152
#define OFF_NORM   65536
#define OFF_FG     74752

static __device__ __align__(16) float g_face[NB * NF * 16];
static __device__ int g_list[NB * NTILE * LIST_STRIDE];

__device__ __forceinline__ float pix_x(int x) {
    const float STEP = 2.0f / 127.0f;
    return (x == 127) ? 1.0f : (-1.0f + x * STEP);
}
__device__ __forceinline__ float pix_y(int y) {
    const float STEP = 2.0f / 127.0f;
    return (y == 127) ? -1.0f : (1.0f - y * STEP);
}

// ---------------------------------------------------------------------------
// Kernel 1: per (batch, face) precompute (unchanged math from passing R1).
// ---------------------------------------------------------------------------
__global__ void prep_kernel(const float* __restrict__ pts,
                            const float* __restrict__ camrot,
                            const float* __restrict__ campos,
                            const float* __restrict__ proj,
                            const int*   __restrict__ faces,
                            float* __restrict__ out_normals) {
    int gid = blockIdx.x * blockDim.x + threadIdx.x;
    if (gid >= NB * NF) return;
    int l = gid / NF, f = gid % NF;

    int vis[3] = {faces[f * 3 + 0], faces[f * 3 + 1], faces[f * 3 + 2]};

    const float* R = camrot + l * 9;
    const float* C = campos + l * 3;
    float p0 = proj[0], p1 = proj[1];

    float vx[3], vy[3], vz[3], sx[3], sy[3];
#pragma unroll
    for (int k = 0; k < 3; k++) {
        const float* P = pts + (l * NP + vis[k]) * 3;
        float q0 = P[0] - C[0], q1 = P[1] - C[1], q2 = P[2] - C[2];
        float X = R[0] * q0 + R[1] * q1 + R[2] * q2;
        float Y = R[3] * q0 + R[4] * q1 + R[5] * q2;
        float Z = R[6] * q0 + R[7] * q1 + R[8] * q2;
        vx[k] = X; vy[k] = Y; vz[k] = Z;
        float zd = Z + EPSF;
        sx[k] = __fdiv_rn(X * p0, zd);
        sy[k] = __fdiv_rn(Y * p1, zd);
    }

    float e1x = vx[1] - vx[0], e1y = vy[1] - vy[0], e1z = vz[1] - vz[0];
    float e2x = vx[2] - vx[0], e2y = vy[2] - vy[0], e2z = vz[2] - vz[0];
    float nx = e1y * e2z - e1z * e2y;
    float ny = e1z * e2x - e1x * e2z;
    float nz = e1x * e2y - e1y * e2x;
    float nn = __fsqrt_rn(nx * nx + ny * ny + nz * nz) + EPSF;
    out_normals[gid * 3 + 0] = __fdiv_rn(nx, nn);
    out_normals[gid * 3 + 1] = __fdiv_rn(ny, nn);
    out_normals[gid * 3 + 2] = __fdiv_rn(nz, nn);

    float ax = sx[0], ay = sy[0], bx = sx[1], by = sy[1], cx = sx[2], cy = sy[2];
    float d = (by - cy) * (ax - cx) + (cx - bx) * (ay - cy);
    float zmax = fmaxf(vz[0], fmaxf(vz[1], vz[2]));
    bool valid = (fabsf(d) > EPSF) && (zmax > EPSF);

    const float STEP = 2.0f / 127.0f;
    float pad = 2.0f * STEP;
    float xmin, xmax, ymin, ymax;
    if (valid) {
        xmin = fminf(ax, fminf(bx, cx)) - pad;
        xmax = fmaxf(ax, fmaxf(bx, cx)) + pad;
        ymin = fminf(ay, fminf(by, cy)) - pad;
        ymax = fmaxf(ay, fmaxf(by, cy)) + pad;
    } else {
        xmin = 3e38f; xmax = -3e38f; ymin = 3e38f; ymax = -3e38f;
    }

    float4* F = reinterpret_cast<float4*>(g_face + gid * 16);
    F[0] = make_float4(by - cy, cx - bx, cy - ay, ax - cx); // e0x,e0y,e1x,e1y
    F[1] = make_float4(cx, cy, d + EPSF, vz[0]);            // cx,cy,denom,z0
    F[2] = make_float4(vz[1], vz[2], 0.0f, 0.0f);           // z1,z2,-,-
    F[3] = make_float4(xmin, xmax, ymin, ymax);             // bbox
}

// ---------------------------------------------------------------------------
// Kernel 2: per (batch, tile) ordered face-list compaction (1 warp each).
// ---------------------------------------------------------------------------
__global__ void build_kernel() {
    int bid = blockIdx.x;
    int l = bid / NTILE, t = bid % NTILE;
    int tx0 = (t & (TILES_X - 1)) * TPX;
    int ty0 = (t / TILES_X) * TPX;
    float xlo = pix_x(tx0),  xhi = pix_x(tx0 + TPX - 1);
    float yhi = pix_y(ty0),  ylo = pix_y(ty0 + TPX - 1);

    int lane = threadIdx.x;
    int* list = g_list + (l * NTILE + t) * LIST_STRIDE;
    int count = 0;
    for (int base = 0; base < NF; base += 32) {
        int f = base + lane;
        const float4 bb = *reinterpret_cast<const float4*>(g_face + (l * NF + f) * 16 + 12);
        bool pred = (bb.x <= xhi) && (bb.y >= xlo) && (bb.z <= yhi) && (bb.w >= ylo);
        unsigned m = __ballot_sync(0xffffffffu, pred);
        if (pred)
            list[1 + count + __popc(m & ((1u << lane) - 1u))] = f;
        count += __popc(m);
    }
    if (lane == 0) list[0] = count;
}

// ---------------------------------------------------------------------------
// Kernel 3: raster + composite + shade.
// One block per 8x8 tile, 128 threads: two 64-thread halves each cover all 64
// pixels on half of the face list; smem-staged 64-face chunks with register
// prefetch; exact-sign numerator prefilter gates the __fdiv_rn slow path.
// ---------------------------------------------------------------------------
__global__ void __launch_bounds__(128)
raster_kernel(const float* __restrict__ ts,
              const int*   __restrict__ faces,
              const float* __restrict__ uv,
              const float* __restrict__ tex,
              float* __restrict__ out) {
    __shared__ float4 stage[2][3][64];
    __shared__ float4 mbuf[64];

    int t = blockIdx.x;
    int half = threadIdx.x >> 6;
    int pix  = threadIdx.x & 63;
    int x = ((t & (TILES_X - 1)) << 3) + (pix & 7);
    int y = ((t / TILES_X) << 3) + (pix >> 3);
    float px = pix_x(x), py = pix_y(y);

    float a0s[3], a1s[3];
    int   fis[3];
    bool  hs[3];

#pragma unroll
    for (int l = 0; l < 3; l++) {
        const int* __restrict__ list = g_list + (l * NTILE + t) * LIST_STRIDE;
        int n = list[0];
        int n0 = (n + 1) >> 1;                  // half0: [0,n0), half1: [n0,n)
        int start = half ? n0 : 0;
        int end   = half ? n  : n0;
        int chunks = (n0 + 63) >> 6;

        const float* fbase = g_face + l * NF * 16;
        float best = 1e10f; int bf = 0; float ba0 = 0.0f, ba1 = 0.0f;

        // prefetch chunk 0
        float4 r0, r1, r2;
        {
            int j = start + pix;
            if (j < end) {
                int f = list[1 + j];
                const float4* fd = reinterpret_cast<const float4*>(fbase + f * 16);
                r0 = fd[0]; r1 = fd[1]; r2 = fd[2];
                r2.z = __int_as_float(f);
            }
        }

        for (int c = 0; c < chunks; c++) {
            int base = start + (c << 6);
            int cnt = end - base; cnt = cnt < 0 ? 0 : (cnt > 64 ? 64 : cnt);
            __syncthreads();
            if (pix < cnt) {
                stage[half][0][pix] = r0;
                stage[half][1][pix] = r1;
                stage[half][2][pix] = r2;
            }
            __syncthreads();
            // prefetch next chunk while computing this one
            {
                int j = base + 64 + pix;
                if (j < end) {
                    int f = list[1 + j];
                    const float4* fd = reinterpret_cast<const float4*>(fbase + f * 16);
                    r0 = fd[0]; r1 = fd[1]; r2 = fd[2];
                    r2.z = __int_as_float(f);
                }
            }
            for (int i = 0; i < cnt; i++) {
                float4 A = stage[half][0][i];     // e0x,e0y,e1x,e1y
                float4 B = stage[half][1][i];     // cx,cy,denom,z0
                float dx = px - B.x, dy = py - B.y;
                float num0 = A.x * dx + A.y * dy;
                float num1 = A.z * dx + A.w * dy;
                float s = (B.z > 0.0f) ? 1.0f : -1.0f;
                if (fminf(num0 * s, num1 * s) >= -1e-30f) {
                    float4 Cz = stage[half][2][i];  // z1,z2,fbits,-
                    float l0 = __fdiv_rn(num0, B.z);
                    float l1 = __fdiv_rn(num1, B.z);
                    float l2 = 1.0f - l0 - l1;
                    float z = l0 * B.w + l1 * Cz.x + l2 * Cz.y;
                    if (l0 >= 0.0f && l1 >= 0.0f && l2 >= 0.0f && z > EPSF && z < best) {
                        best = z; bf = __float_as_int(Cz.z); ba0 = l0; ba1 = l1;
                    }
                }
            }
        }

        // merge halves: strict '<' keeps earlier-list (half0) winner on ties,
        // matching argmin first-occurrence semantics.
        __syncthreads();
        if (half == 1)
            mbuf[pix] = make_float4(best, ba0, ba1, __int_as_float(bf));
        __syncthreads();
        if (half == 0) {
            float4 m = mbuf[pix];
            if (m.x < best) { best = m.x; ba0 = m.y; ba1 = m.z; bf = __float_as_int(m.w); }
            a0s[l] = ba0; a1s[l] = ba1; fis[l] = bf; hs[l] = (best < 1e9f);
        }
    }

    if (half != 0) return;

    // stable argsort of -ts[:,2] over 3 layers
    float k0 = -ts[2], k1 = -ts[5], k2 = -ts[8];
    int o0 = 0; float kv = k0;
    if (k1 < kv) { o0 = 1; kv = k1; }
    if (k2 < kv) { o0 = 2; kv = k2; }
    int r0i = (o0 == 0) ? 1 : 0;
    int r1i = (o0 == 2) ? 1 : 2;
    float kr0 = (r0i == 0) ? k0 : k1;
    float kr1 = (r1i == 1) ? k1 : k2;
    int o1, o2;
    if (kr0 <= kr1) { o1 = r0i; o2 = r1i; }
    else            { o1 = r1i; o2 = r0i; }

    int sel = o0;
    if (hs[o1]) sel = o1;
    if (hs[o2]) sel = o2;

    float c0 = 0.0f, c1 = 0.0f, c2 = 0.0f, hard = 0.0f;
    if (hs[sel]) {
        hard = 1.0f;
        int f = fis[sel];
        int i0 = faces[f * 3 + 0];
        int i1 = faces[f * 3 + 1];
        int i2 = faces[f * 3 + 2];
        const float* U = uv + sel * NP * 2;
        float l0 = a0s[sel], l1 = a1s[sel], l2 = 1.0f - l0 - l1;
        float u = l0 * U[2 * i0]     + l1 * U[2 * i1]     + l2 * U[2 * i2];
        float v = l0 * U[2 * i0 + 1] + l1 * U[2 * i1 + 1] + l2 * U[2 * i2 + 1];
        u = fminf(fmaxf(u, 0.0f), 1.0f);
        v = fminf(fmaxf(v, 0.0f), 1.0f);
        int txi = (int)rintf(u * 511.0f);
        int tyi = (int)rintf((1.0f - v) * 511.0f);
        const float* T = tex + sel * 3 * 512 * 512 + tyi * 512 + txi;
        c0 = T[0];
        c1 = T[262144];
        c2 = T[524288];
    }

    int pid = y * IMG + x;
    out[OFF_IM + pid * 3 + 0] = c0;
    out[OFF_IM + pid * 3 + 1] = c1;
    out[OFF_IM + pid * 3 + 2] = c2;
    out[OFF_PROB + pid] = hard;
    out[OFF_FG + pid]   = hard;
}

// ---------------------------------------------------------------------------
extern "C" void kernel_launch(void* const* d_in, const int* in_sizes, int n_in,
                              void* d_out, int out_size) {
    const float* points = (const float*)d_in[0];
    const float* camrot = (const float*)d_in[1];
    const float* campos = (const float*)d_in[2];
    const float* proj   = (const float*)d_in[3];
    const float* uv     = (const float*)d_in[4];
    const float* tex    = (const float*)d_in[5];
    const float* ts     = (const float*)d_in[6];
    const int*   faces  = (const int*)d_in[7];
    float* out = (float*)d_out;

    prep_kernel<<<(NB * NF + 255) / 256, 256>>>(points, camrot, campos, proj,
                                                faces, out + OFF_NORM);
    build_kernel<<<NB * NTILE, 32>>>();
    raster_kernel<<<NTILE, 128>>>(ts, faces, uv, tex, out);
}

// round 3
// speedup vs baseline: 17.8785x; 3.0032x over previous
#include <cuda_runtime.h>
#include <math.h>

#define EPSF 1e-8f
#define NB 3
#define NF 1024
#define NP 768
#define IMG 128
#define TPX 8          // 8x8 pixel tiles
#define TILES_X 16
#define NTILE 256      // 16x16 tiles
#define LIST_STRIDE (NF + 1)

// out offsets (f32 elements)
#define OFF_IM     0
#define OFF_PROB   49152
#define OFF_NORM   65536
#define OFF_FG     74752

static __device__ __align__(16) float g_face[NB * NF * 12];
static __device__ __align__(16) float4 g_bbox[NB * NF];
static __device__ int g_list[NB * NTILE * LIST_STRIDE];

__device__ __forceinline__ float pix_x(int x) {
    const float STEP = 2.0f / 127.0f;
    return (x == 127) ? 1.0f : (-1.0f + x * STEP);
}
__device__ __forceinline__ float pix_y(int y) {
    const float STEP = 2.0f / 127.0f;
    return (y == 127) ? -1.0f : (1.0f - y * STEP);
}

// ---------------------------------------------------------------------------
// Kernel 1: per (batch, face) precompute. Stores reciprocal denom so the
// raster inner loop is divide-free.
// ---------------------------------------------------------------------------
__global__ void prep_kernel(const float* __restrict__ pts,
                            const float* __restrict__ camrot,
                            const float* __restrict__ campos,
                            const float* __restrict__ proj,
                            const int*   __restrict__ faces,
                            float* __restrict__ out_normals) {
    int gid = blockIdx.x * blockDim.x + threadIdx.x;
    if (gid >= NB * NF) return;
    int l = gid / NF, f = gid % NF;

    int vis[3] = {faces[f * 3 + 0], faces[f * 3 + 1], faces[f * 3 + 2]};

    const float* R = camrot + l * 9;
    const float* C = campos + l * 3;
    float p0 = proj[0], p1 = proj[1];

    float vx[3], vy[3], vz[3], sx[3], sy[3];
#pragma unroll
    for (int k = 0; k < 3; k++) {
        const float* P = pts + (l * NP + vis[k]) * 3;
        float q0 = P[0] - C[0], q1 = P[1] - C[1], q2 = P[2] - C[2];
        float X = R[0] * q0 + R[1] * q1 + R[2] * q2;
        float Y = R[3] * q0 + R[4] * q1 + R[5] * q2;
        float Z = R[6] * q0 + R[7] * q1 + R[8] * q2;
        vx[k] = X; vy[k] = Y; vz[k] = Z;
        float zd = Z + EPSF;
        sx[k] = __fdiv_rn(X * p0, zd);
        sy[k] = __fdiv_rn(Y * p1, zd);
    }

    float e1x = vx[1] - vx[0], e1y = vy[1] - vy[0], e1z = vz[1] - vz[0];
    float e2x = vx[2] - vx[0], e2y = vy[2] - vy[0], e2z = vz[2] - vz[0];
    float nx = e1y * e2z - e1z * e2y;
    float ny = e1z * e2x - e1x * e2z;
    float nz = e1x * e2y - e1y * e2x;
    float nn = __fsqrt_rn(nx * nx + ny * ny + nz * nz) + EPSF;
    out_normals[gid * 3 + 0] = __fdiv_rn(nx, nn);
    out_normals[gid * 3 + 1] = __fdiv_rn(ny, nn);
    out_normals[gid * 3 + 2] = __fdiv_rn(nz, nn);

    float ax = sx[0], ay = sy[0], bx = sx[1], by = sy[1], cx = sx[2], cy = sy[2];
    float d = (by - cy) * (ax - cx) + (cx - bx) * (ay - cy);
    float zmax = fmaxf(vz[0], fmaxf(vz[1], vz[2]));
    bool valid = (fabsf(d) > EPSF) && (zmax > EPSF);

    const float STEP = 2.0f / 127.0f;
    float pad = 2.0f * STEP;
    float xmin, xmax, ymin, ymax;
    if (valid) {
        xmin = fminf(ax, fminf(bx, cx)) - pad;
        xmax = fmaxf(ax, fmaxf(bx, cx)) + pad;
        ymin = fminf(ay, fminf(by, cy)) - pad;
        ymax = fmaxf(ay, fmaxf(by, cy)) + pad;
    } else {
        xmin = 3e38f; xmax = -3e38f; ymin = 3e38f; ymax = -3e38f;
    }

    float rd = __frcp_rn(d + EPSF);     // ~1ulp; slack vs 1e-3 tolerance is huge

    float4* F = reinterpret_cast<float4*>(g_face + gid * 12);
    F[0] = make_float4(by - cy, cx - bx, cy - ay, ax - cx); // e0x,e0y,e1x,e1y
    F[1] = make_float4(cx, cy, rd, vz[0]);                  // cx,cy,rdenom,z0
    F[2] = make_float4(vz[1], vz[2], 0.0f, 0.0f);           // z1,z2,-,-
    g_bbox[gid] = make_float4(xmin, xmax, ymin, ymax);      // SoA for build
}

// ---------------------------------------------------------------------------
// Kernel 2: per (batch, tile) ordered face-list compaction (1 warp each).
// Coalesced SoA bbox loads (512B per warp iteration).
// ---------------------------------------------------------------------------
__global__ void build_kernel() {
    int bid = blockIdx.x;
    int l = bid / NTILE, t = bid % NTILE;
    int tx0 = (t & (TILES_X - 1)) * TPX;
    int ty0 = (t / TILES_X) * TPX;
    float xlo = pix_x(tx0),  xhi = pix_x(tx0 + TPX - 1);
    float yhi = pix_y(ty0),  ylo = pix_y(ty0 + TPX - 1);

    int lane = threadIdx.x;
    int* list = g_list + (l * NTILE + t) * LIST_STRIDE;
    int count = 0;
    for (int base = 0; base < NF; base += 32) {
        int f = base + lane;
        const float4 bb = g_bbox[l * NF + f];
        bool pred = (bb.x <= xhi) && (bb.y >= xlo) && (bb.z <= yhi) && (bb.w >= ylo);
        unsigned m = __ballot_sync(0xffffffffu, pred);
        if (pred)
            list[1 + count + __popc(m & ((1u << lane) - 1u))] = f;
        count += __popc(m);
    }
    if (lane == 0) list[0] = count;
}

// ---------------------------------------------------------------------------
// Kernel 3: raster + composite + shade. 256 threads: four 64-thread groups,
// each covering all 64 pixels on a contiguous quarter of the face list.
// Branchless divide-free inner loop over smem-staged faces; ordered merge.
// ---------------------------------------------------------------------------
__global__ void __launch_bounds__(256)
raster_kernel(const float* __restrict__ ts,
              const int*   __restrict__ faces,
              const float* __restrict__ uv,
              const float* __restrict__ tex,
              float* __restrict__ out) {
    __shared__ float4 stage[4][3][64];
    __shared__ float4 mbuf[3][64];

    int t = blockIdx.x;
    int g   = threadIdx.x >> 6;
    int pix = threadIdx.x & 63;
    int x = ((t & (TILES_X - 1)) << 3) + (pix & 7);
    int y = ((t / TILES_X) << 3) + (pix >> 3);
    float px = pix_x(x), py = pix_y(y);

    float a0s[3], a1s[3];
    int   fis[3];
    bool  hs[3];

#pragma unroll
    for (int l = 0; l < 3; l++) {
        const int* __restrict__ list = g_list + (l * NTILE + t) * LIST_STRIDE;
        int n = list[0];
        int start = (n * g) >> 2;
        int end   = (n * (g + 1)) >> 2;
        int chunksU = (((n + 3) >> 2) + 63) >> 6;   // uniform across groups

        const float* fbase = g_face + l * NF * 12;
        float best = 1e10f; int bf = 0; float ba0 = 0.0f, ba1 = 0.0f;

        // register prefetch of first chunk
        float4 r0, r1, r2;
        {
            int j = start + pix;
            if (j < end) {
                int f = list[1 + j];
                const float4* fd = reinterpret_cast<const float4*>(fbase + f * 12);
                r0 = fd[0]; r1 = fd[1]; r2 = fd[2];
                r2.z = __int_as_float(f);
            }
        }

        for (int c = 0; c < chunksU; c++) {
            int base = start + (c << 6);
            int cnt = end - base; cnt = cnt < 0 ? 0 : (cnt > 64 ? 64 : cnt);
            __syncthreads();
            if (pix < cnt) {
                stage[g][0][pix] = r0;
                stage[g][1][pix] = r1;
                stage[g][2][pix] = r2;
            }
            __syncthreads();
            {   // prefetch next chunk
                int j = base + 64 + pix;
                if (j < end) {
                    int f = list[1 + j];
                    const float4* fd = reinterpret_cast<const float4*>(fbase + f * 12);
                    r0 = fd[0]; r1 = fd[1]; r2 = fd[2];
                    r2.z = __int_as_float(f);
                }
            }
            for (int i = 0; i < cnt; i++) {
                float4 A = stage[g][0][i];     // e0x,e0y,e1x,e1y
                float4 B = stage[g][1][i];     // cx,cy,rdenom,z0
                float4 Z = stage[g][2][i];     // z1,z2,fbits,-
                float dx = px - B.x, dy = py - B.y;
                float l0 = (A.x * dx + A.y * dy) * B.z;
                float l1 = (A.z * dx + A.w * dy) * B.z;
                float l2 = 1.0f - l0 - l1;
                float z  = l0 * B.w + l1 * Z.x + l2 * Z.y;
                bool ok = (l0 >= 0.0f) & (l1 >= 0.0f) & (l2 >= 0.0f) &
                          (z > EPSF) & (z < best);
                best = ok ? z : best;
                bf   = ok ? __float_as_int(Z.z) : bf;
                ba0  = ok ? l0 : ba0;
                ba1  = ok ? l1 : ba1;
            }
        }

        // ordered merge: group order = list order, strict '<' keeps earliest,
        // matching argmin first-occurrence semantics.
        __syncthreads();
        if (g > 0)
            mbuf[g - 1][pix] = make_float4(best, ba0, ba1, __int_as_float(bf));
        __syncthreads();
        if (g == 0) {
#pragma unroll
            for (int q = 0; q < 3; q++) {
                float4 m = mbuf[q][pix];
                if (m.x < best) { best = m.x; ba0 = m.y; ba1 = m.z; bf = __float_as_int(m.w); }
            }
            a0s[l] = ba0; a1s[l] = ba1; fis[l] = bf; hs[l] = (best < 1e9f);
        }
    }

    if (g != 0) return;

    // stable argsort of -ts[:,2] over 3 layers
    float k0 = -ts[2], k1 = -ts[5], k2 = -ts[8];
    int o0 = 0; float kv = k0;
    if (k1 < kv) { o0 = 1; kv = k1; }
    if (k2 < kv) { o0 = 2; kv = k2; }
    int r0i = (o0 == 0) ? 1 : 0;
    int r1i = (o0 == 2) ? 1 : 2;
    float kr0 = (r0i == 0) ? k0 : k1;
    float kr1 = (r1i == 1) ? k1 : k2;
    int o1, o2;
    if (kr0 <= kr1) { o1 = r0i; o2 = r1i; }
    else            { o1 = r1i; o2 = r0i; }

    int sel = o0;
    if (hs[o1]) sel = o1;
    if (hs[o2]) sel = o2;

    float c0 = 0.0f, c1 = 0.0f, c2 = 0.0f, hard = 0.0f;
    if (hs[sel]) {
        hard = 1.0f;
        int f = fis[sel];
        int i0 = faces[f * 3 + 0];
        int i1 = faces[f * 3 + 1];
        int i2 = faces[f * 3 + 2];
        const float* U = uv + sel * NP * 2;
        float l0 = a0s[sel], l1 = a1s[sel], l2 = 1.0f - l0 - l1;
        float u = l0 * U[2 * i0]     + l1 * U[2 * i1]     + l2 * U[2 * i2];
        float v = l0 * U[2 * i0 + 1] + l1 * U[2 * i1 + 1] + l2 * U[2 * i2 + 1];
        u = fminf(fmaxf(u, 0.0f), 1.0f);
        v = fminf(fmaxf(v, 0.0f), 1.0f);
        int txi = (int)rintf(u * 511.0f);
        int tyi = (int)rintf((1.0f - v) * 511.0f);
        const float* T = tex + sel * 3 * 512 * 512 + tyi * 512 + txi;
        c0 = T[0];
        c1 = T[262144];
        c2 = T[524288];
    }

    int pid = y * IMG + x;
    out[OFF_IM + pid * 3 + 0] = c0;
    out[OFF_IM + pid * 3 + 1] = c1;
    out[OFF_IM + pid * 3 + 2] = c2;
    out[OFF_PROB + pid] = hard;
    out[OFF_FG + pid]   = hard;
}

// Dummy 4th launch: makes launches-per-call = 4 so ncu's fixed capture index
// (== 2 mod 4) lands on raster_kernel next profile.
__global__ void dummy_kernel() {}

// ---------------------------------------------------------------------------
extern "C" void kernel_launch(void* const* d_in, const int* in_sizes, int n_in,
                              void* d_out, int out_size) {
    const float* points = (const float*)d_in[0];
    const float* camrot = (const float*)d_in[1];
    const float* campos = (const float*)d_in[2];
    const float* proj   = (const float*)d_in[3];
    const float* uv     = (const float*)d_in[4];
    const float* tex    = (const float*)d_in[5];
    const float* ts     = (const float*)d_in[6];
    const int*   faces  = (const int*)d_in[7];
    float* out = (float*)d_out;

    prep_kernel<<<(NB * NF + 255) / 256, 256>>>(points, camrot, campos, proj,
                                                faces, out + OFF_NORM);
    build_kernel<<<NB * NTILE, 32>>>();
    raster_kernel<<<NTILE, 256>>>(ts, faces, uv, tex, out);
    dummy_kernel<<<1, 32>>>();
}

// round 4
// speedup vs baseline: 19.3873x; 1.0844x over previous
#include <cuda_runtime.h>
#include <math.h>

#define EPSF 1e-8f
#define NB 3
#define NF 1024
#define NP 768
#define IMG 128
#define TPX 8          // 8x8 pixel tiles
#define TILES_X 16
#define NTILE 256      // 16x16 tiles
#define LIST_STRIDE (NF + 1)

// out offsets (f32 elements)
#define OFF_IM     0
#define OFF_PROB   49152
#define OFF_NORM   65536
#define OFF_FG     74752

static __device__ __align__(16) float g_face[NB * NF * 12];
static __device__ __align__(16) float4 g_bbox[NB * NF];
static __device__ __align__(16) float4 g_edgeA[NB * NF];  // s*e0x, s*e0y, s*e1x, s*e1y
static __device__ __align__(16) float4 g_edgeB[NB * NF];  // cx, cy, s*(d+eps), 0
static __device__ int g_list[NB * NTILE * LIST_STRIDE];

__device__ __forceinline__ float pix_x(int x) {
    const float STEP = 2.0f / 127.0f;
    return (x == 127) ? 1.0f : (-1.0f + x * STEP);
}
__device__ __forceinline__ float pix_y(int y) {
    const float STEP = 2.0f / 127.0f;
    return (y == 127) ? -1.0f : (1.0f - y * STEP);
}

// ---------------------------------------------------------------------------
// Kernel 1: per (batch, face) precompute: transform, screen coords, edge
// coefficients (plus sign-normalized copies for tile culling), bbox, normal.
// ---------------------------------------------------------------------------
__global__ void prep_kernel(const float* __restrict__ pts,
                            const float* __restrict__ camrot,
                            const float* __restrict__ campos,
                            const float* __restrict__ proj,
                            const int*   __restrict__ faces,
                            float* __restrict__ out_normals) {
    int gid = blockIdx.x * blockDim.x + threadIdx.x;
    if (gid >= NB * NF) return;
    int l = gid / NF, f = gid % NF;

    int vis[3] = {faces[f * 3 + 0], faces[f * 3 + 1], faces[f * 3 + 2]};

    const float* R = camrot + l * 9;
    const float* C = campos + l * 3;
    float p0 = proj[0], p1 = proj[1];

    float vx[3], vy[3], vz[3], sx[3], sy[3];
#pragma unroll
    for (int k = 0; k < 3; k++) {
        const float* P = pts + (l * NP + vis[k]) * 3;
        float q0 = P[0] - C[0], q1 = P[1] - C[1], q2 = P[2] - C[2];
        float X = R[0] * q0 + R[1] * q1 + R[2] * q2;
        float Y = R[3] * q0 + R[4] * q1 + R[5] * q2;
        float Z = R[6] * q0 + R[7] * q1 + R[8] * q2;
        vx[k] = X; vy[k] = Y; vz[k] = Z;
        float zd = Z + EPSF;
        sx[k] = __fdiv_rn(X * p0, zd);
        sy[k] = __fdiv_rn(Y * p1, zd);
    }

    float e1x = vx[1] - vx[0], e1y = vy[1] - vy[0], e1z = vz[1] - vz[0];
    float e2x = vx[2] - vx[0], e2y = vy[2] - vy[0], e2z = vz[2] - vz[0];
    float nx = e1y * e2z - e1z * e2y;
    float ny = e1z * e2x - e1x * e2z;
    float nz = e1x * e2y - e1y * e2x;
    float nn = __fsqrt_rn(nx * nx + ny * ny + nz * nz) + EPSF;
    out_normals[gid * 3 + 0] = __fdiv_rn(nx, nn);
    out_normals[gid * 3 + 1] = __fdiv_rn(ny, nn);
    out_normals[gid * 3 + 2] = __fdiv_rn(nz, nn);

    float ax = sx[0], ay = sy[0], bx = sx[1], by = sy[1], cx = sx[2], cy = sy[2];
    float d = (by - cy) * (ax - cx) + (cx - bx) * (ay - cy);
    float zmax = fmaxf(vz[0], fmaxf(vz[1], vz[2]));
    bool valid = (fabsf(d) > EPSF) && (zmax > EPSF);

    const float STEP = 2.0f / 127.0f;
    float pad = 1.0f * STEP;    // 1px pad; FP noise scale is ~1e-6 NDC
    float xmin, xmax, ymin, ymax;
    if (valid) {
        xmin = fminf(ax, fminf(bx, cx)) - pad;
        xmax = fmaxf(ax, fmaxf(bx, cx)) + pad;
        ymin = fminf(ay, fminf(by, cy)) - pad;
        ymax = fmaxf(ay, fmaxf(by, cy)) + pad;
    } else {
        xmin = 3e38f; xmax = -3e38f; ymin = 3e38f; ymax = -3e38f;
    }

    float dn = d + EPSF;
    float rd = __frcp_rn(dn);
    float s  = (dn > 0.0f) ? 1.0f : -1.0f;

    float e0xc = by - cy, e0yc = cx - bx, e1xc = cy - ay, e1yc = ax - cx;

    float4* F = reinterpret_cast<float4*>(g_face + gid * 12);
    F[0] = make_float4(e0xc, e0yc, e1xc, e1yc);         // e0x,e0y,e1x,e1y
    F[1] = make_float4(cx, cy, rd, vz[0]);              // cx,cy,rdenom,z0
    F[2] = make_float4(vz[1], vz[2], 0.0f, 0.0f);       // z1,z2,-,-
    g_bbox[gid]  = make_float4(xmin, xmax, ymin, ymax);
    g_edgeA[gid] = make_float4(s * e0xc, s * e0yc, s * e1xc, s * e1yc);
    g_edgeB[gid] = make_float4(cx, cy, s * dn, 0.0f);
}

// ---------------------------------------------------------------------------
// Kernel 2: per (batch, tile) ordered face-list compaction with exact
// conservative triangle-vs-tile culling (bbox + 3 edge-function rect maxima).
// ---------------------------------------------------------------------------
__global__ void build_kernel() {
    int bid = blockIdx.x;
    int l = bid / NTILE, t = bid % NTILE;
    int tx0 = (t & (TILES_X - 1)) * TPX;
    int ty0 = (t / TILES_X) * TPX;
    float xlo = pix_x(tx0),  xhi = pix_x(tx0 + TPX - 1);
    float yhi = pix_y(ty0),  ylo = pix_y(ty0 + TPX - 1);
    const float MARGIN = -1e-6f;

    int lane = threadIdx.x;
    int* list = g_list + (l * NTILE + t) * LIST_STRIDE;
    int count = 0;
    for (int base = 0; base < NF; base += 32) {
        int f = base + lane;
        int gi = l * NF + f;
        const float4 bb = g_bbox[gi];
        bool pred = (bb.x <= xhi) && (bb.y >= xlo) && (bb.z <= yhi) && (bb.w >= ylo);
        if (pred) {
            float4 A = g_edgeA[gi];   // s*e0x, s*e0y, s*e1x, s*e1y
            float4 B = g_edgeB[gi];   // cx, cy, s*dn
            // max over tile rect of each (sign-normalized) edge function
            float m0 = A.x * ((A.x > 0.0f ? xhi : xlo) - B.x)
                     + A.y * ((A.y > 0.0f ? yhi : ylo) - B.y);
            float m1 = A.z * ((A.z > 0.0f ? xhi : xlo) - B.x)
                     + A.w * ((A.w > 0.0f ? yhi : ylo) - B.y);
            float b2x = -(A.x + A.z), b2y = -(A.y + A.w);
            float m2 = B.z
                     + b2x * ((b2x > 0.0f ? xhi : xlo) - B.x)
                     + b2y * ((b2y > 0.0f ? yhi : ylo) - B.y);
            pred = (m0 >= MARGIN) && (m1 >= MARGIN) && (m2 >= MARGIN);
        }
        unsigned m = __ballot_sync(0xffffffffu, pred);
        if (pred)
            list[1 + count + __popc(m & ((1u << lane) - 1u))] = f;
        count += __popc(m);
    }
    if (lane == 0) list[0] = count;
}

// ---------------------------------------------------------------------------
// Kernel 3: raster + composite + shade. 256 threads: four 64-thread groups,
// each covering all 64 pixels on a contiguous quarter of the face list.
// ---------------------------------------------------------------------------
__global__ void __launch_bounds__(256)
raster_kernel(const float* __restrict__ ts,
              const int*   __restrict__ faces,
              const float* __restrict__ uv,
              const float* __restrict__ tex,
              float* __restrict__ out) {
    __shared__ float4 stage[4][3][64];
    __shared__ float4 mbuf[3][64];

    int t = blockIdx.x;
    int g   = threadIdx.x >> 6;
    int pix = threadIdx.x & 63;
    int x = ((t & (TILES_X - 1)) << 3) + (pix & 7);
    int y = ((t / TILES_X) << 3) + (pix >> 3);
    float px = pix_x(x), py = pix_y(y);

    float a0s[3], a1s[3];
    int   fis[3];
    bool  hs[3];

#pragma unroll
    for (int l = 0; l < 3; l++) {
        const int* __restrict__ list = g_list + (l * NTILE + t) * LIST_STRIDE;
        int n = list[0];
        int start = (n * g) >> 2;
        int end   = (n * (g + 1)) >> 2;
        int chunksU = (((n + 3) >> 2) + 63) >> 6;

        const float* fbase = g_face + l * NF * 12;
        float best = 1e10f; int bf = 0; float ba0 = 0.0f, ba1 = 0.0f;

        float4 r0, r1, r2;
        {
            int j = start + pix;
            if (j < end) {
                int f = list[1 + j];
                const float4* fd = reinterpret_cast<const float4*>(fbase + f * 12);
                r0 = fd[0]; r1 = fd[1]; r2 = fd[2];
                r2.z = __int_as_float(f);
            }
        }

        for (int c = 0; c < chunksU; c++) {
            int base = start + (c << 6);
            int cnt = end - base; cnt = cnt < 0 ? 0 : (cnt > 64 ? 64 : cnt);
            __syncthreads();
            if (pix < cnt) {
                stage[g][0][pix] = r0;
                stage[g][1][pix] = r1;
                stage[g][2][pix] = r2;
            }
            __syncthreads();
            {
                int j = base + 64 + pix;
                if (j < end) {
                    int f = list[1 + j];
                    const float4* fd = reinterpret_cast<const float4*>(fbase + f * 12);
                    r0 = fd[0]; r1 = fd[1]; r2 = fd[2];
                    r2.z = __int_as_float(f);
                }
            }
            for (int i = 0; i < cnt; i++) {
                float4 A = stage[g][0][i];
                float4 B = stage[g][1][i];
                float4 Z = stage[g][2][i];
                float dx = px - B.x, dy = py - B.y;
                float l0 = (A.x * dx + A.y * dy) * B.z;
                float l1 = (A.z * dx + A.w * dy) * B.z;
                float l2 = 1.0f - l0 - l1;
                float z  = l0 * B.w + l1 * Z.x + l2 * Z.y;
                bool ok = (l0 >= 0.0f) & (l1 >= 0.0f) & (l2 >= 0.0f) &
                          (z > EPSF) & (z < best);
                best = ok ? z : best;
                bf   = ok ? __float_as_int(Z.z) : bf;
                ba0  = ok ? l0 : ba0;
                ba1  = ok ? l1 : ba1;
            }
        }

        __syncthreads();
        if (g > 0)
            mbuf[g - 1][pix] = make_float4(best, ba0, ba1, __int_as_float(bf));
        __syncthreads();
        if (g == 0) {
#pragma unroll
            for (int q = 0; q < 3; q++) {
                float4 m = mbuf[q][pix];
                if (m.x < best) { best = m.x; ba0 = m.y; ba1 = m.z; bf = __float_as_int(m.w); }
            }
            a0s[l] = ba0; a1s[l] = ba1; fis[l] = bf; hs[l] = (best < 1e9f);
        }
    }

    if (g != 0) return;

    float k0 = -ts[2], k1 = -ts[5], k2 = -ts[8];
    int o0 = 0; float kv = k0;
    if (k1 < kv) { o0 = 1; kv = k1; }
    if (k2 < kv) { o0 = 2; kv = k2; }
    int r0i = (o0 == 0) ? 1 : 0;
    int r1i = (o0 == 2) ? 1 : 2;
    float kr0 = (r0i == 0) ? k0 : k1;
    float kr1 = (r1i == 1) ? k1 : k2;
    int o1, o2;
    if (kr0 <= kr1) { o1 = r0i; o2 = r1i; }
    else            { o1 = r1i; o2 = r0i; }

    int sel = o0;
    if (hs[o1]) sel = o1;
    if (hs[o2]) sel = o2;

    float c0 = 0.0f, c1 = 0.0f, c2 = 0.0f, hard = 0.0f;
    if (hs[sel]) {
        hard = 1.0f;
        int f = fis[sel];
        int i0 = faces[f * 3 + 0];
        int i1 = faces[f * 3 + 1];
        int i2 = faces[f * 3 + 2];
        const float* U = uv + sel * NP * 2;
        float l0 = a0s[sel], l1 = a1s[sel], l2 = 1.0f - l0 - l1;
        float u = l0 * U[2 * i0]     + l1 * U[2 * i1]     + l2 * U[2 * i2];
        float v = l0 * U[2 * i0 + 1] + l1 * U[2 * i1 + 1] + l2 * U[2 * i2 + 1];
        u = fminf(fmaxf(u, 0.0f), 1.0f);
        v = fminf(fmaxf(v, 0.0f), 1.0f);
        int txi = (int)rintf(u * 511.0f);
        int tyi = (int)rintf((1.0f - v) * 511.0f);
        const float* T = tex + sel * 3 * 512 * 512 + tyi * 512 + txi;
        c0 = T[0];
        c1 = T[262144];
        c2 = T[524288];
    }

    int pid = y * IMG + x;
    out[OFF_IM + pid * 3 + 0] = c0;
    out[OFF_IM + pid * 3 + 1] = c1;
    out[OFF_IM + pid * 3 + 2] = c2;
    out[OFF_PROB + pid] = hard;
    out[OFF_FG + pid]   = hard;
}

// Dummy: keeps launches-per-call = 4 with raster at position 3, where the
// ncu capture index (A ≡ 3 mod 12) lands.
__global__ void dummy_kernel() {}

// ---------------------------------------------------------------------------
extern "C" void kernel_launch(void* const* d_in, const int* in_sizes, int n_in,
                              void* d_out, int out_size) {
    const float* points = (const float*)d_in[0];
    const float* camrot = (const float*)d_in[1];
    const float* campos = (const float*)d_in[2];
    const float* proj   = (const float*)d_in[3];
    const float* uv     = (const float*)d_in[4];
    const float* tex    = (const float*)d_in[5];
    const float* ts     = (const float*)d_in[6];
    const int*   faces  = (const int*)d_in[7];
    float* out = (float*)d_out;

    prep_kernel<<<(NB * NF + 255) / 256, 256>>>(points, camrot, campos, proj,
                                                faces, out + OFF_NORM);
    build_kernel<<<NB * NTILE, 32>>>();
    dummy_kernel<<<1, 32>>>();
    raster_kernel<<<NTILE, 256>>>(ts, faces, uv, tex, out);
}

// round 5
// speedup vs baseline: 34.4000x; 1.7744x over previous
#include <cuda_runtime.h>
#include <math.h>

#define EPSF 1e-8f
#define NB 3
#define NF 1024
#define NP 768
#define IMG 128
#define TPX 8          // 8x8 pixel tiles
#define TILES_X 16
#define NTILE 256      // 16x16 tiles

// out offsets (f32 elements)
#define OFF_IM     0
#define OFF_PROB   49152
#define OFF_NORM   65536
#define OFF_FG     74752

static __device__ __align__(16) float g_face[NB * NF * 12];
static __device__ __align__(16) float4 g_bbox[NB * NF];
static __device__ __align__(16) float4 g_edgeA[NB * NF];  // s*e0x, s*e0y, s*e1x, s*e1y
static __device__ __align__(16) float4 g_edgeB[NB * NF];  // cx, cy, s*(d+eps), 0

__device__ __forceinline__ float pix_x(int x) {
    const float STEP = 2.0f / 127.0f;
    return (x == 127) ? 1.0f : (-1.0f + x * STEP);
}
__device__ __forceinline__ float pix_y(int y) {
    const float STEP = 2.0f / 127.0f;
    return (y == 127) ? -1.0f : (1.0f - y * STEP);
}

// ---------------------------------------------------------------------------
// Kernel 1: per (batch, face) precompute (identical math to passing R4).
// ---------------------------------------------------------------------------
__global__ void prep_kernel(const float* __restrict__ pts,
                            const float* __restrict__ camrot,
                            const float* __restrict__ campos,
                            const float* __restrict__ proj,
                            const int*   __restrict__ faces,
                            float* __restrict__ out_normals) {
    int gid = blockIdx.x * blockDim.x + threadIdx.x;
    if (gid >= NB * NF) return;
    int l = gid / NF, f = gid % NF;

    int vis[3] = {faces[f * 3 + 0], faces[f * 3 + 1], faces[f * 3 + 2]};

    const float* R = camrot + l * 9;
    const float* C = campos + l * 3;
    float p0 = proj[0], p1 = proj[1];

    float vx[3], vy[3], vz[3], sx[3], sy[3];
#pragma unroll
    for (int k = 0; k < 3; k++) {
        const float* P = pts + (l * NP + vis[k]) * 3;
        float q0 = P[0] - C[0], q1 = P[1] - C[1], q2 = P[2] - C[2];
        float X = R[0] * q0 + R[1] * q1 + R[2] * q2;
        float Y = R[3] * q0 + R[4] * q1 + R[5] * q2;
        float Z = R[6] * q0 + R[7] * q1 + R[8] * q2;
        vx[k] = X; vy[k] = Y; vz[k] = Z;
        float zd = Z + EPSF;
        sx[k] = __fdiv_rn(X * p0, zd);
        sy[k] = __fdiv_rn(Y * p1, zd);
    }

    float e1x = vx[1] - vx[0], e1y = vy[1] - vy[0], e1z = vz[1] - vz[0];
    float e2x = vx[2] - vx[0], e2y = vy[2] - vy[0], e2z = vz[2] - vz[0];
    float nx = e1y * e2z - e1z * e2y;
    float ny = e1z * e2x - e1x * e2z;
    float nz = e1x * e2y - e1y * e2x;
    float nn = __fsqrt_rn(nx * nx + ny * ny + nz * nz) + EPSF;
    out_normals[gid * 3 + 0] = __fdiv_rn(nx, nn);
    out_normals[gid * 3 + 1] = __fdiv_rn(ny, nn);
    out_normals[gid * 3 + 2] = __fdiv_rn(nz, nn);

    float ax = sx[0], ay = sy[0], bx = sx[1], by = sy[1], cx = sx[2], cy = sy[2];
    float d = (by - cy) * (ax - cx) + (cx - bx) * (ay - cy);
    float zmax = fmaxf(vz[0], fmaxf(vz[1], vz[2]));
    bool valid = (fabsf(d) > EPSF) && (zmax > EPSF);

    const float STEP = 2.0f / 127.0f;
    float pad = 1.0f * STEP;
    float xmin, xmax, ymin, ymax;
    if (valid) {
        xmin = fminf(ax, fminf(bx, cx)) - pad;
        xmax = fmaxf(ax, fmaxf(bx, cx)) + pad;
        ymin = fminf(ay, fminf(by, cy)) - pad;
        ymax = fmaxf(ay, fmaxf(by, cy)) + pad;
    } else {
        xmin = 3e38f; xmax = -3e38f; ymin = 3e38f; ymax = -3e38f;
    }

    float dn = d + EPSF;
    float rd = __frcp_rn(dn);
    float s  = (dn > 0.0f) ? 1.0f : -1.0f;
    float e0xc = by - cy, e0yc = cx - bx, e1xc = cy - ay, e1yc = ax - cx;

    float4* F = reinterpret_cast<float4*>(g_face + gid * 12);
    F[0] = make_float4(e0xc, e0yc, e1xc, e1yc);
    F[1] = make_float4(cx, cy, rd, vz[0]);
    F[2] = make_float4(vz[1], vz[2], 0.0f, 0.0f);
    g_bbox[gid]  = make_float4(xmin, xmax, ymin, ymax);
    g_edgeA[gid] = make_float4(s * e0xc, s * e0yc, s * e1xc, s * e1yc);
    g_edgeB[gid] = make_float4(cx, cy, s * dn, 0.0f);
}

// ---------------------------------------------------------------------------
// Kernel 2 (fused): in-block list build + raster + composite + shade.
// 768 threads = 24 warps.
//   Phase A: 24 warps = 3 layers x 8 face-segments; ballot-compaction into
//            per-warp temp, prefix, ordered copy -> smem lists (ascending).
//   Phase B: 12 groups of 64 px = (layer, quarter) concurrently; smem-staged
//            chunks; inner arithmetic bit-identical to the R4 passing kernel.
//   Phase C: ordered strict-'<' merge (argmin-first semantics) + composite.
// ---------------------------------------------------------------------------
__global__ void __launch_bounds__(768)
raster_fused(const float* __restrict__ ts,
             const int*   __restrict__ faces,
             const float* __restrict__ uv,
             const float* __restrict__ tex,
             float* __restrict__ out) {
    __shared__ unsigned short slist[NB][NF];
    __shared__ int s_cnt[24];
    __shared__ int s_off[NB][9];
    __shared__ __align__(16) char s_buf[12 * 3 * 64 * 16];   // stage | temp | mbuf

    unsigned short (*temp)[128] = reinterpret_cast<unsigned short (*)[128]>(s_buf);
    float4 (*stage)[3][64]      = reinterpret_cast<float4 (*)[3][64]>(s_buf);

    int t = blockIdx.x;
    int tid = threadIdx.x;
    int w = tid >> 5, lane = tid & 31;

    int tx0 = (t & (TILES_X - 1)) * TPX;
    int ty0 = (t / TILES_X) * TPX;
    float xlo = pix_x(tx0),  xhi = pix_x(tx0 + TPX - 1);
    float yhi = pix_y(ty0),  ylo = pix_y(ty0 + TPX - 1);
    const float MARGIN = -1e-6f;

    // ---- Phase A: build lists ----
    {
        int layer = w >> 3, seg = w & 7;
        int cnt = 0;
        unsigned short* tw = temp[w];
#pragma unroll
        for (int it = 0; it < 4; it++) {
            int f = seg * 128 + it * 32 + lane;
            int gi = layer * NF + f;
            const float4 bb = g_bbox[gi];
            bool pred = (bb.x <= xhi) && (bb.y >= xlo) && (bb.z <= yhi) && (bb.w >= ylo);
            if (pred) {
                float4 A = g_edgeA[gi];
                float4 B = g_edgeB[gi];
                float m0 = A.x * ((A.x > 0.0f ? xhi : xlo) - B.x)
                         + A.y * ((A.y > 0.0f ? yhi : ylo) - B.y);
                float m1 = A.z * ((A.z > 0.0f ? xhi : xlo) - B.x)
                         + A.w * ((A.w > 0.0f ? yhi : ylo) - B.y);
                float b2x = -(A.x + A.z), b2y = -(A.y + A.w);
                float m2 = B.z
                         + b2x * ((b2x > 0.0f ? xhi : xlo) - B.x)
                         + b2y * ((b2y > 0.0f ? yhi : ylo) - B.y);
                pred = (m0 >= MARGIN) && (m1 >= MARGIN) && (m2 >= MARGIN);
            }
            unsigned m = __ballot_sync(0xffffffffu, pred);
            if (pred)
                tw[cnt + __popc(m & ((1u << lane) - 1u))] = (unsigned short)f;
            cnt += __popc(m);
        }
        if (lane == 0) s_cnt[w] = cnt;
    }
    __syncthreads();
    if (tid < 3) {
        int acc = 0;
        s_off[tid][0] = 0;
#pragma unroll
        for (int sgi = 0; sgi < 8; sgi++) {
            acc += s_cnt[tid * 8 + sgi];
            s_off[tid][sgi + 1] = acc;
        }
    }
    __syncthreads();
#pragma unroll
    for (int l = 0; l < NB; l++) {
        int tot = s_off[l][8];
        for (int i = tid; i < tot; i += 768) {
            int sgi = 0;
            while (i >= s_off[l][sgi + 1]) sgi++;
            slist[l][i] = temp[l * 8 + sgi][i - s_off[l][sgi]];
        }
    }
    __syncthreads();   // lists done; temp region free for stage reuse

    // ---- Phase B: raster, 12 concurrent (layer, quarter) groups ----
    int g   = tid >> 6;          // 0..11
    int pix = tid & 63;
    int layer = g >> 2, q = g & 3;

    int x = tx0 + (pix & 7);
    int y = ty0 + (pix >> 3);
    float px = pix_x(x), py = pix_y(y);

    int n = s_off[layer][8];
    int start = (n * q) >> 2;
    int end   = (n * (q + 1)) >> 2;
    int Mx = s_off[0][8];
    Mx = Mx > s_off[1][8] ? Mx : s_off[1][8];
    Mx = Mx > s_off[2][8] ? Mx : s_off[2][8];
    int chunks = (((Mx + 3) >> 2) + 63) >> 6;

    const float* fbase = g_face + layer * NF * 12;
    float best = 1e10f; int bf = 0; float ba0 = 0.0f, ba1 = 0.0f;

    float4 r0, r1, r2;
    {
        int j = start + pix;
        if (j < end) {
            int f = slist[layer][j];
            const float4* fd = reinterpret_cast<const float4*>(fbase + f * 12);
            r0 = fd[0]; r1 = fd[1]; r2 = fd[2];
            r2.z = __int_as_float(f);
        }
    }

    for (int c = 0; c < chunks; c++) {
        int base = start + (c << 6);
        int cnt = end - base; cnt = cnt < 0 ? 0 : (cnt > 64 ? 64 : cnt);
        __syncthreads();
        if (pix < cnt) {
            stage[g][0][pix] = r0;
            stage[g][1][pix] = r1;
            stage[g][2][pix] = r2;
        }
        __syncthreads();
        {
            int j = base + 64 + pix;
            if (j < end) {
                int f = slist[layer][j];
                const float4* fd = reinterpret_cast<const float4*>(fbase + f * 12);
                r0 = fd[0]; r1 = fd[1]; r2 = fd[2];
                r2.z = __int_as_float(f);
            }
        }
        for (int i = 0; i < cnt; i++) {
            float4 A = stage[g][0][i];
            float4 B = stage[g][1][i];
            float4 Z = stage[g][2][i];
            float dx = px - B.x, dy = py - B.y;
            float l0 = (A.x * dx + A.y * dy) * B.z;
            float l1 = (A.z * dx + A.w * dy) * B.z;
            float l2 = 1.0f - l0 - l1;
            float z  = l0 * B.w + l1 * Z.x + l2 * Z.y;
            bool ok = (l0 >= 0.0f) & (l1 >= 0.0f) & (l2 >= 0.0f) &
                      (z > EPSF) & (z < best);
            best = ok ? z : best;
            bf   = ok ? __float_as_int(Z.z) : bf;
            ba0  = ok ? l0 : ba0;
            ba1  = ok ? l1 : ba1;
        }
    }

    // ---- Phase C: merge + composite (stage memory reused as mbuf) ----
    __syncthreads();
    float4* mbuf = reinterpret_cast<float4*>(s_buf);   // [12][64]
    mbuf[g * 64 + pix] = make_float4(best, ba0, ba1, __int_as_float(bf));
    __syncthreads();

    if (g != 0) return;

    float a0s[3], a1s[3];
    int   fis[3];
    bool  hs[3];
#pragma unroll
    for (int l = 0; l < NB; l++) {
        float mb = 1e10f; float m0 = 0.0f, m1 = 0.0f; int mf = 0;
#pragma unroll
        for (int qq = 0; qq < 4; qq++) {
            float4 m = mbuf[(l * 4 + qq) * 64 + pix];
            if (m.x < mb) { mb = m.x; m0 = m.y; m1 = m.z; mf = __float_as_int(m.w); }
        }
        a0s[l] = m0; a1s[l] = m1; fis[l] = mf; hs[l] = (mb < 1e9f);
    }

    float k0 = -ts[2], k1 = -ts[5], k2 = -ts[8];
    int o0 = 0; float kv = k0;
    if (k1 < kv) { o0 = 1; kv = k1; }
    if (k2 < kv) { o0 = 2; kv = k2; }
    int r0i = (o0 == 0) ? 1 : 0;
    int r1i = (o0 == 2) ? 1 : 2;
    float kr0 = (r0i == 0) ? k0 : k1;
    float kr1 = (r1i == 1) ? k1 : k2;
    int o1, o2;
    if (kr0 <= kr1) { o1 = r0i; o2 = r1i; }
    else            { o1 = r1i; o2 = r0i; }

    int sel = o0;
    if (hs[o1]) sel = o1;
    if (hs[o2]) sel = o2;

    float c0 = 0.0f, c1 = 0.0f, c2 = 0.0f, hard = 0.0f;
    if (hs[sel]) {
        hard = 1.0f;
        int f = fis[sel];
        int i0 = faces[f * 3 + 0];
        int i1 = faces[f * 3 + 1];
        int i2 = faces[f * 3 + 2];
        const float* U = uv + sel * NP * 2;
        float l0 = a0s[sel], l1 = a1s[sel], l2 = 1.0f - l0 - l1;
        float u = l0 * U[2 * i0]     + l1 * U[2 * i1]     + l2 * U[2 * i2];
        float v = l0 * U[2 * i0 + 1] + l1 * U[2 * i1 + 1] + l2 * U[2 * i2 + 1];
        u = fminf(fmaxf(u, 0.0f), 1.0f);
        v = fminf(fmaxf(v, 0.0f), 1.0f);
        int txi = (int)rintf(u * 511.0f);
        int tyi = (int)rintf((1.0f - v) * 511.0f);
        const float* T = tex + sel * 3 * 512 * 512 + tyi * 512 + txi;
        c0 = T[0];
        c1 = T[262144];
        c2 = T[524288];
    }

    int pid = y * IMG + x;
    out[OFF_IM + pid * 3 + 0] = c0;
    out[OFF_IM + pid * 3 + 1] = c1;
    out[OFF_IM + pid * 3 + 2] = c2;
    out[OFF_PROB + pid] = hard;
    out[OFF_FG + pid]   = hard;
}

// ---------------------------------------------------------------------------
extern "C" void kernel_launch(void* const* d_in, const int* in_sizes, int n_in,
                              void* d_out, int out_size) {
    const float* points = (const float*)d_in[0];
    const float* camrot = (const float*)d_in[1];
    const float* campos = (const float*)d_in[2];
    const float* proj   = (const float*)d_in[3];
    const float* uv     = (const float*)d_in[4];
    const float* tex    = (const float*)d_in[5];
    const float* ts     = (const float*)d_in[6];
    const int*   faces  = (const int*)d_in[7];
    float* out = (float*)d_out;

    prep_kernel<<<(NB * NF + 255) / 256, 256>>>(points, camrot, campos, proj,
                                                faces, out + OFF_NORM);
    raster_fused<<<NTILE, 768>>>(ts, faces, uv, tex, out);
}

// round 6
// speedup vs baseline: 56.7513x; 1.6497x over previous
#include <cuda_runtime.h>
#include <math.h>

#define EPSF 1e-8f
#define NB 3
#define NF 1024
#define NP 768
#define IMG 128
#define NPIX (IMG * IMG)

// out offsets (f32 elements)
#define OFF_IM     0
#define OFF_PROB   49152
#define OFF_NORM   65536
#define OFF_FG     74752

static __device__ __align__(16) float g_face[NB * NF * 12];
static __device__ __align__(16) float4 g_bbox[NB * NF];
static __device__ unsigned long long g_zbuf[NB * NPIX];

__device__ __forceinline__ float pix_x(int x) {
    const float STEP = 2.0f / 127.0f;
    return (x == 127) ? 1.0f : (-1.0f + x * STEP);
}
__device__ __forceinline__ float pix_y(int y) {
    const float STEP = 2.0f / 127.0f;
    return (y == 127) ? -1.0f : (1.0f - y * STEP);
}

// ---------------------------------------------------------------------------
// Kernel: z-buffer init (0xFF.. = empty; any valid key is smaller).
// ---------------------------------------------------------------------------
__global__ void zinit_kernel() {
    int i = blockIdx.x * blockDim.x + threadIdx.x;
    if (i < NB * NPIX) g_zbuf[i] = 0xFFFFFFFFFFFFFFFFull;
}

// ---------------------------------------------------------------------------
// Kernel: per (batch, face) precompute (identical math to passing R5).
// ---------------------------------------------------------------------------
__global__ void prep_kernel(const float* __restrict__ pts,
                            const float* __restrict__ camrot,
                            const float* __restrict__ campos,
                            const float* __restrict__ proj,
                            const int*   __restrict__ faces,
                            float* __restrict__ out_normals) {
    int gid = blockIdx.x * blockDim.x + threadIdx.x;
    if (gid >= NB * NF) return;
    int l = gid / NF, f = gid % NF;

    int vis[3] = {faces[f * 3 + 0], faces[f * 3 + 1], faces[f * 3 + 2]};

    const float* R = camrot + l * 9;
    const float* C = campos + l * 3;
    float p0 = proj[0], p1 = proj[1];

    float vx[3], vy[3], vz[3], sx[3], sy[3];
#pragma unroll
    for (int k = 0; k < 3; k++) {
        const float* P = pts + (l * NP + vis[k]) * 3;
        float q0 = P[0] - C[0], q1 = P[1] - C[1], q2 = P[2] - C[2];
        float X = R[0] * q0 + R[1] * q1 + R[2] * q2;
        float Y = R[3] * q0 + R[4] * q1 + R[5] * q2;
        float Z = R[6] * q0 + R[7] * q1 + R[8] * q2;
        vx[k] = X; vy[k] = Y; vz[k] = Z;
        float zd = Z + EPSF;
        sx[k] = __fdiv_rn(X * p0, zd);
        sy[k] = __fdiv_rn(Y * p1, zd);
    }

    float e1x = vx[1] - vx[0], e1y = vy[1] - vy[0], e1z = vz[1] - vz[0];
    float e2x = vx[2] - vx[0], e2y = vy[2] - vy[0], e2z = vz[2] - vz[0];
    float nx = e1y * e2z - e1z * e2y;
    float ny = e1z * e2x - e1x * e2z;
    float nz = e1x * e2y - e1y * e2x;
    float nn = __fsqrt_rn(nx * nx + ny * ny + nz * nz) + EPSF;
    out_normals[gid * 3 + 0] = __fdiv_rn(nx, nn);
    out_normals[gid * 3 + 1] = __fdiv_rn(ny, nn);
    out_normals[gid * 3 + 2] = __fdiv_rn(nz, nn);

    float ax = sx[0], ay = sy[0], bx = sx[1], by = sy[1], cx = sx[2], cy = sy[2];
    float d = (by - cy) * (ax - cx) + (cx - bx) * (ay - cy);
    float zmax = fmaxf(vz[0], fmaxf(vz[1], vz[2]));
    bool valid = (fabsf(d) > EPSF) && (zmax > EPSF);

    const float STEP = 2.0f / 127.0f;
    float pad = 1.0f * STEP;
    float xmin, xmax, ymin, ymax;
    if (valid) {
        xmin = fminf(ax, fminf(bx, cx)) - pad;
        xmax = fmaxf(ax, fmaxf(bx, cx)) + pad;
        ymin = fminf(ay, fminf(by, cy)) - pad;
        ymax = fmaxf(ay, fmaxf(by, cy)) + pad;
    } else {
        xmin = 3e38f; xmax = -3e38f; ymin = 3e38f; ymax = -3e38f;
    }

    float dn = d + EPSF;
    float rd = __frcp_rn(dn);

    float4* F = reinterpret_cast<float4*>(g_face + gid * 12);
    F[0] = make_float4(by - cy, cx - bx, cy - ay, ax - cx); // e0x,e0y,e1x,e1y
    F[1] = make_float4(cx, cy, rd, vz[0]);                  // cx,cy,rdenom,z0
    F[2] = make_float4(vz[1], vz[2], 0.0f, 0.0f);           // z1,z2,-,-
    g_bbox[gid] = make_float4(xmin, xmax, ymin, ymax);
}

// ---------------------------------------------------------------------------
// Kernel: scatter rasterization. One warp per (layer, face); lanes sweep the
// padded bbox row-wise. Winner selection via packed u64 atomicMin:
//   key = (bits(z) << 32) | face  ->  min z, tie -> min face = argmin-first.
// ---------------------------------------------------------------------------
__global__ void __launch_bounds__(256)
scatter_kernel() {
    int wg = (blockIdx.x * blockDim.x + threadIdx.x) >> 5;
    int lane = threadIdx.x & 31;
    if (wg >= NB * NF) return;
    int layer = wg >> 10;
    int f = wg & (NF - 1);

    float4 bb = g_bbox[wg];
    if (bb.x > bb.y) return;            // invalid face

    const float INV_STEP = 63.5f;       // 1 / (2/127)
    int x0 = max(0, (int)floorf((bb.x + 1.0f) * INV_STEP));
    int x1 = min(IMG - 1, (int)ceilf((bb.y + 1.0f) * INV_STEP));
    int y0 = max(0, (int)floorf((1.0f - bb.w) * INV_STEP));
    int y1 = min(IMG - 1, (int)ceilf((1.0f - bb.z) * INV_STEP));
    if (x0 > x1 || y0 > y1) return;

    const float4* fd = reinterpret_cast<const float4*>(g_face + wg * 12);
    float4 A = fd[0];   // e0x,e0y,e1x,e1y
    float4 B = fd[1];   // cx,cy,rdenom,z0
    float4 Z = fd[2];   // z1,z2,-,-

    unsigned long long* zb = g_zbuf + layer * NPIX;

    for (int y = y0; y <= y1; y++) {
        float py = pix_y(y);
        float dy = py - B.y;
        for (int x = x0 + lane; x <= x1; x += 32) {
            float px = pix_x(x);
            float dx = px - B.x;
            float l0 = (A.x * dx + A.y * dy) * B.z;
            float l1 = (A.z * dx + A.w * dy) * B.z;
            float l2 = 1.0f - l0 - l1;
            float z  = l0 * B.w + l1 * Z.x + l2 * Z.y;
            if (l0 >= 0.0f && l1 >= 0.0f && l2 >= 0.0f && z > EPSF) {
                unsigned long long key =
                    ((unsigned long long)__float_as_uint(z) << 32) | (unsigned)f;
                atomicMin(&zb[y * IMG + x], key);
            }
        }
    }
}

// ---------------------------------------------------------------------------
// Kernel: shade. One thread per pixel: read 3 layer winners, recompute
// barycentrics, stable-argsort composite, texture fetch, write all outputs.
// ---------------------------------------------------------------------------
__global__ void __launch_bounds__(256)
shade_kernel(const float* __restrict__ ts,
             const int*   __restrict__ faces,
             const float* __restrict__ uv,
             const float* __restrict__ tex,
             float* __restrict__ out) {
    int pid = blockIdx.x * blockDim.x + threadIdx.x;
    if (pid >= NPIX) return;
    int x = pid & (IMG - 1), y = pid >> 7;
    float px = pix_x(x), py = pix_y(y);

    float a0s[3], a1s[3];
    int   fis[3];
    bool  hs[3];
#pragma unroll
    for (int l = 0; l < NB; l++) {
        unsigned long long key = g_zbuf[l * NPIX + pid];
        bool h = (key != 0xFFFFFFFFFFFFFFFFull);
        int f = (int)(key & 0xFFFFFFFFu);
        float l0 = 0.0f, l1 = 0.0f;
        if (h) {
            const float4* fd = reinterpret_cast<const float4*>(g_face + (l * NF + f) * 12);
            float4 A = fd[0];
            float4 B = fd[1];
            float dx = px - B.x, dy = py - B.y;
            l0 = (A.x * dx + A.y * dy) * B.z;
            l1 = (A.z * dx + A.w * dy) * B.z;
        }
        a0s[l] = l0; a1s[l] = l1; fis[l] = f; hs[l] = h;
    }

    // stable argsort of -ts[:,2]
    float k0 = -ts[2], k1 = -ts[5], k2 = -ts[8];
    int o0 = 0; float kv = k0;
    if (k1 < kv) { o0 = 1; kv = k1; }
    if (k2 < kv) { o0 = 2; kv = k2; }
    int r0i = (o0 == 0) ? 1 : 0;
    int r1i = (o0 == 2) ? 1 : 2;
    float kr0 = (r0i == 0) ? k0 : k1;
    float kr1 = (r1i == 1) ? k1 : k2;
    int o1, o2;
    if (kr0 <= kr1) { o1 = r0i; o2 = r1i; }
    else            { o1 = r1i; o2 = r0i; }

    int sel = o0;
    if (hs[o1]) sel = o1;
    if (hs[o2]) sel = o2;

    float c0 = 0.0f, c1 = 0.0f, c2 = 0.0f, hard = 0.0f;
    if (hs[sel]) {
        hard = 1.0f;
        int f = fis[sel];
        int i0 = faces[f * 3 + 0];
        int i1 = faces[f * 3 + 1];
        int i2 = faces[f * 3 + 2];
        const float* U = uv + sel * NP * 2;
        float l0 = a0s[sel], l1 = a1s[sel], l2 = 1.0f - l0 - l1;
        float u = l0 * U[2 * i0]     + l1 * U[2 * i1]     + l2 * U[2 * i2];
        float v = l0 * U[2 * i0 + 1] + l1 * U[2 * i1 + 1] + l2 * U[2 * i2 + 1];
        u = fminf(fmaxf(u, 0.0f), 1.0f);
        v = fminf(fmaxf(v, 0.0f), 1.0f);
        int txi = (int)rintf(u * 511.0f);
        int tyi = (int)rintf((1.0f - v) * 511.0f);
        const float* T = tex + sel * 3 * 512 * 512 + tyi * 512 + txi;
        c0 = T[0];
        c1 = T[262144];
        c2 = T[524288];
    }

    out[OFF_IM + pid * 3 + 0] = c0;
    out[OFF_IM + pid * 3 + 1] = c1;
    out[OFF_IM + pid * 3 + 2] = c2;
    out[OFF_PROB + pid] = hard;
    out[OFF_FG + pid]   = hard;
}

// ---------------------------------------------------------------------------
extern "C" void kernel_launch(void* const* d_in, const int* in_sizes, int n_in,
                              void* d_out, int out_size) {
    const float* points = (const float*)d_in[0];
    const float* camrot = (const float*)d_in[1];
    const float* campos = (const float*)d_in[2];
    const float* proj   = (const float*)d_in[3];
    const float* uv     = (const float*)d_in[4];
    const float* tex    = (const float*)d_in[5];
    const float* ts     = (const float*)d_in[6];
    const int*   faces  = (const int*)d_in[7];
    float* out = (float*)d_out;

    prep_kernel<<<(NB * NF + 255) / 256, 256>>>(points, camrot, campos, proj,
                                                faces, out + OFF_NORM);
    zinit_kernel<<<(NB * NPIX + 255) / 256, 256>>>();
    scatter_kernel<<<(NB * NF * 32 + 255) / 256, 256>>>();
    shade_kernel<<<(NPIX + 255) / 256, 256>>>(ts, faces, uv, tex, out);
}

// round 7
// speedup vs baseline: 62.5746x; 1.1026x over previous
#include <cuda_runtime.h>
#include <math.h>

#define EPSF 1e-8f
#define NB 3
#define NF 1024
#define NP 768
#define IMG 128
#define NPIX (IMG * IMG)

// out offsets (f32 elements)
#define OFF_IM     0
#define OFF_PROB   49152
#define OFF_NORM   65536
#define OFF_FG     74752

static __device__ __align__(16) float g_face[NB * NF * 12];
static __device__ unsigned long long g_zbuf[NB * NPIX];

__device__ __forceinline__ float pix_x(int x) {
    const float STEP = 2.0f / 127.0f;
    return (x == 127) ? 1.0f : (-1.0f + x * STEP);
}
__device__ __forceinline__ float pix_y(int y) {
    const float STEP = 2.0f / 127.0f;
    return (y == 127) ? -1.0f : (1.0f - y * STEP);
}

// ---------------------------------------------------------------------------
// Kernel 1: z-buffer init (0xFF.. = empty; any valid key is smaller).
// ---------------------------------------------------------------------------
__global__ void zinit_kernel() {
    int i = blockIdx.x * blockDim.x + threadIdx.x;
    if (i < NB * NPIX) g_zbuf[i] = 0xFFFFFFFFFFFFFFFFull;
}

// ---------------------------------------------------------------------------
// Kernel 2 (fused): per-(layer,face) prep + scatter rasterization.
// One warp per (layer, face). Every lane redundantly computes the face's
// setup in registers (identical math to the passing R6 prep), lane 0 writes
// g_face + the output normal, then all lanes sweep the padded bbox with the
// packed-u64 atomicMin z-test (min z, tie -> min face = argmin-first).
// ---------------------------------------------------------------------------
__global__ void __launch_bounds__(256)
scatter_kernel(const float* __restrict__ pts,
               const float* __restrict__ camrot,
               const float* __restrict__ campos,
               const float* __restrict__ proj,
               const int*   __restrict__ faces,
               float* __restrict__ out_normals) {
    int wg = (blockIdx.x * blockDim.x + threadIdx.x) >> 5;
    int lane = threadIdx.x & 31;
    if (wg >= NB * NF) return;
    int l = wg >> 10;
    int f = wg & (NF - 1);

    // ---- per-face prep (all lanes redundantly; identical math to R6 prep) --
    int vis[3] = {faces[f * 3 + 0], faces[f * 3 + 1], faces[f * 3 + 2]};
    const float* R = camrot + l * 9;
    const float* C = campos + l * 3;
    float p0 = proj[0], p1 = proj[1];

    float vx[3], vy[3], vz[3], sx[3], sy[3];
#pragma unroll
    for (int k = 0; k < 3; k++) {
        const float* P = pts + (l * NP + vis[k]) * 3;
        float q0 = P[0] - C[0], q1 = P[1] - C[1], q2 = P[2] - C[2];
        float X = R[0] * q0 + R[1] * q1 + R[2] * q2;
        float Y = R[3] * q0 + R[4] * q1 + R[5] * q2;
        float Z = R[6] * q0 + R[7] * q1 + R[8] * q2;
        vx[k] = X; vy[k] = Y; vz[k] = Z;
        float zd = Z + EPSF;
        sx[k] = __fdiv_rn(X * p0, zd);
        sy[k] = __fdiv_rn(Y * p1, zd);
    }

    if (lane == 0) {
        float e1xx = vx[1] - vx[0], e1yy = vy[1] - vy[0], e1zz = vz[1] - vz[0];
        float e2xx = vx[2] - vx[0], e2yy = vy[2] - vy[0], e2zz = vz[2] - vz[0];
        float nx = e1yy * e2zz - e1zz * e2yy;
        float ny = e1zz * e2xx - e1xx * e2zz;
        float nz = e1xx * e2yy - e1yy * e2xx;
        float nn = __fsqrt_rn(nx * nx + ny * ny + nz * nz) + EPSF;
        out_normals[wg * 3 + 0] = __fdiv_rn(nx, nn);
        out_normals[wg * 3 + 1] = __fdiv_rn(ny, nn);
        out_normals[wg * 3 + 2] = __fdiv_rn(nz, nn);
    }

    float ax = sx[0], ay = sy[0], bx = sx[1], by = sy[1], cx = sx[2], cy = sy[2];
    float d = (by - cy) * (ax - cx) + (cx - bx) * (ay - cy);
    float zmax = fmaxf(vz[0], fmaxf(vz[1], vz[2]));
    bool valid = (fabsf(d) > EPSF) && (zmax > EPSF);

    float dn = d + EPSF;
    float rd = __frcp_rn(dn);
    float4 A = make_float4(by - cy, cx - bx, cy - ay, ax - cx);
    float4 B = make_float4(cx, cy, rd, vz[0]);
    float4 Z = make_float4(vz[1], vz[2], 0.0f, 0.0f);

    if (lane == 0) {
        float4* F = reinterpret_cast<float4*>(g_face + wg * 12);
        F[0] = A; F[1] = B; F[2] = Z;
    }

    if (!valid) return;

    const float STEP = 2.0f / 127.0f;
    float pad = 1.0f * STEP;
    float xmin = fminf(ax, fminf(bx, cx)) - pad;
    float xmax = fmaxf(ax, fmaxf(bx, cx)) + pad;
    float ymin = fminf(ay, fminf(by, cy)) - pad;
    float ymax = fmaxf(ay, fmaxf(by, cy)) + pad;

    const float INV_STEP = 63.5f;       // 1 / (2/127)
    int x0 = max(0, (int)floorf((xmin + 1.0f) * INV_STEP));
    int x1 = min(IMG - 1, (int)ceilf((xmax + 1.0f) * INV_STEP));
    int y0 = max(0, (int)floorf((1.0f - ymax) * INV_STEP));
    int y1 = min(IMG - 1, (int)ceilf((1.0f - ymin) * INV_STEP));
    if (x0 > x1 || y0 > y1) return;

    unsigned long long* zb = g_zbuf + l * NPIX;

    for (int y = y0; y <= y1; y++) {
        float py = pix_y(y);
        float dy = py - B.y;
        for (int x = x0 + lane; x <= x1; x += 32) {
            float px = pix_x(x);
            float dx = px - B.x;
            float l0 = (A.x * dx + A.y * dy) * B.z;
            float l1 = (A.z * dx + A.w * dy) * B.z;
            float l2 = 1.0f - l0 - l1;
            float z  = l0 * B.w + l1 * Z.x + l2 * Z.y;
            if (l0 >= 0.0f && l1 >= 0.0f && l2 >= 0.0f && z > EPSF) {
                unsigned long long key =
                    ((unsigned long long)__float_as_uint(z) << 32) | (unsigned)f;
                atomicMin(&zb[y * IMG + x], key);
            }
        }
    }
}

// ---------------------------------------------------------------------------
// Kernel 3: shade. 192 threads / 64 pixels per block: 3 threads per pixel
// (one per layer) resolve winner -> barycentric -> uv -> texel coords in
// parallel; then 64 threads composite + fetch texture + write outputs.
// ---------------------------------------------------------------------------
__global__ void __launch_bounds__(192)
shade_kernel(const float* __restrict__ ts,
             const int*   __restrict__ faces,
             const float* __restrict__ uv,
             const float* __restrict__ tex,
             float* __restrict__ out) {
    __shared__ int   s_tc[NB][64];      // packed (tyi<<16)|txi, -1 = miss
    int tid = threadIdx.x;
    int l = tid / 64;                   // layer for phase A
    int p = tid % 64;
    int pid = blockIdx.x * 64 + p;
    int x = pid & (IMG - 1), y = pid >> 7;
    float px = pix_x(x), py = pix_y(y);

    // ---- Phase A: per (layer, pixel) winner resolve ----
    {
        unsigned long long key = g_zbuf[l * NPIX + pid];
        int packed = -1;
        if (key != 0xFFFFFFFFFFFFFFFFull) {
            int f = (int)(key & 0xFFFFFFFFu);
            const float4* fd = reinterpret_cast<const float4*>(g_face + (l * NF + f) * 12);
            float4 A = fd[0];
            float4 B = fd[1];
            float dx = px - B.x, dy = py - B.y;
            float l0 = (A.x * dx + A.y * dy) * B.z;
            float l1 = (A.z * dx + A.w * dy) * B.z;
            float l2 = 1.0f - l0 - l1;
            int i0 = faces[f * 3 + 0];
            int i1 = faces[f * 3 + 1];
            int i2 = faces[f * 3 + 2];
            const float* U = uv + l * NP * 2;
            float u = l0 * U[2 * i0]     + l1 * U[2 * i1]     + l2 * U[2 * i2];
            float v = l0 * U[2 * i0 + 1] + l1 * U[2 * i1 + 1] + l2 * U[2 * i2 + 1];
            u = fminf(fmaxf(u, 0.0f), 1.0f);
            v = fminf(fmaxf(v, 0.0f), 1.0f);
            int txi = (int)rintf(u * 511.0f);
            int tyi = (int)rintf((1.0f - v) * 511.0f);
            packed = (tyi << 16) | txi;
        }
        s_tc[l][p] = packed;
    }
    __syncthreads();

    // ---- Phase B: composite + texture + write (threads 0..63) ----
    if (tid >= 64) return;

    // stable argsort of -ts[:,2]
    float k0 = -ts[2], k1 = -ts[5], k2 = -ts[8];
    int o0 = 0; float kv = k0;
    if (k1 < kv) { o0 = 1; kv = k1; }
    if (k2 < kv) { o0 = 2; kv = k2; }
    int r0i = (o0 == 0) ? 1 : 0;
    int r1i = (o0 == 2) ? 1 : 2;
    float kr0 = (r0i == 0) ? k0 : k1;
    float kr1 = (r1i == 1) ? k1 : k2;
    int o1, o2;
    if (kr0 <= kr1) { o1 = r0i; o2 = r1i; }
    else            { o1 = r1i; o2 = r0i; }

    int pc0 = s_tc[o0][p], pc1 = s_tc[o1][p], pc2 = s_tc[o2][p];
    int sel = o0, pc = pc0;
    if (pc1 >= 0) { sel = o1; pc = pc1; }
    if (pc2 >= 0) { sel = o2; pc = pc2; }

    float c0 = 0.0f, c1 = 0.0f, c2 = 0.0f, hard = 0.0f;
    if (pc >= 0) {
        hard = 1.0f;
        int txi = pc & 0xFFFF, tyi = pc >> 16;
        const float* T = tex + sel * 3 * 512 * 512 + tyi * 512 + txi;
        c0 = T[0];
        c1 = T[262144];
        c2 = T[524288];
    }

    out[OFF_IM + pid * 3 + 0] = c0;
    out[OFF_IM + pid * 3 + 1] = c1;
    out[OFF_IM + pid * 3 + 2] = c2;
    out[OFF_PROB + pid] = hard;
    out[OFF_FG + pid]   = hard;
}

// ---------------------------------------------------------------------------
extern "C" void kernel_launch(void* const* d_in, const int* in_sizes, int n_in,
                              void* d_out, int out_size) {
    const float* points = (const float*)d_in[0];
    const float* camrot = (const float*)d_in[1];
    const float* campos = (const float*)d_in[2];
    const float* proj   = (const float*)d_in[3];
    const float* uv     = (const float*)d_in[4];
    const float* tex    = (const float*)d_in[5];
    const float* ts     = (const float*)d_in[6];
    const int*   faces  = (const int*)d_in[7];
    float* out = (float*)d_out;

    zinit_kernel<<<(NB * NPIX + 255) / 256, 256>>>();
    scatter_kernel<<<(NB * NF * 32 + 255) / 256, 256>>>(points, camrot, campos,
                                                        proj, faces, out + OFF_NORM);
    shade_kernel<<<NPIX / 64, 192>>>(ts, faces, uv, tex, out);
}

// round 8
// speedup vs baseline: 62.8090x; 1.0037x over previous
#include <cuda_runtime.h>
#include <math.h>

#define EPSF 1e-8f
#define NB 3
#define NF 1024
#define NP 768
#define IMG 128
#define NPIX (IMG * IMG)

// out offsets (f32 elements)
#define OFF_IM     0
#define OFF_PROB   49152
#define OFF_NORM   65536
#define OFF_FG     74752

static __device__ __align__(16) float g_face[NB * NF * 12];
// Inverted-key z-buffer: 0 = empty (module-load default & post-shade state).
// key = (~bits(z) << 32) | (0xFFFFFFFF - f); atomicMax => min z, tie min f.
static __device__ unsigned long long g_zbuf[NB * NPIX];

__device__ __forceinline__ float pix_x(int x) {
    const float STEP = 2.0f / 127.0f;
    return (x == 127) ? 1.0f : (-1.0f + x * STEP);
}
__device__ __forceinline__ float pix_y(int y) {
    const float STEP = 2.0f / 127.0f;
    return (y == 127) ? -1.0f : (1.0f - y * STEP);
}

// ---------------------------------------------------------------------------
// Kernel 1 (fused): per-(layer,face) prep + scatter rasterization.
// One warp per (layer, face); all lanes redundantly compute face setup in
// registers (identical math to the passing R7 kernel), lane 0 writes g_face +
// the output normal, then lanes sweep the padded bbox with atomicMax z-test.
// ---------------------------------------------------------------------------
__global__ void __launch_bounds__(256)
scatter_kernel(const float* __restrict__ pts,
               const float* __restrict__ camrot,
               const float* __restrict__ campos,
               const float* __restrict__ proj,
               const int*   __restrict__ faces,
               float* __restrict__ out_normals) {
    int wg = (blockIdx.x * blockDim.x + threadIdx.x) >> 5;
    int lane = threadIdx.x & 31;
    if (wg >= NB * NF) return;
    int l = wg >> 10;
    int f = wg & (NF - 1);

    int vis[3] = {faces[f * 3 + 0], faces[f * 3 + 1], faces[f * 3 + 2]};
    const float* R = camrot + l * 9;
    const float* C = campos + l * 3;
    float p0 = proj[0], p1 = proj[1];

    float vx[3], vy[3], vz[3], sx[3], sy[3];
#pragma unroll
    for (int k = 0; k < 3; k++) {
        const float* P = pts + (l * NP + vis[k]) * 3;
        float q0 = P[0] - C[0], q1 = P[1] - C[1], q2 = P[2] - C[2];
        float X = R[0] * q0 + R[1] * q1 + R[2] * q2;
        float Y = R[3] * q0 + R[4] * q1 + R[5] * q2;
        float Z = R[6] * q0 + R[7] * q1 + R[8] * q2;
        vx[k] = X; vy[k] = Y; vz[k] = Z;
        float zd = Z + EPSF;
        sx[k] = __fdiv_rn(X * p0, zd);
        sy[k] = __fdiv_rn(Y * p1, zd);
    }

    if (lane == 0) {
        float e1xx = vx[1] - vx[0], e1yy = vy[1] - vy[0], e1zz = vz[1] - vz[0];
        float e2xx = vx[2] - vx[0], e2yy = vy[2] - vy[0], e2zz = vz[2] - vz[0];
        float nx = e1yy * e2zz - e1zz * e2yy;
        float ny = e1zz * e2xx - e1xx * e2zz;
        float nz = e1xx * e2yy - e1yy * e2xx;
        float nn = __fsqrt_rn(nx * nx + ny * ny + nz * nz) + EPSF;
        out_normals[wg * 3 + 0] = __fdiv_rn(nx, nn);
        out_normals[wg * 3 + 1] = __fdiv_rn(ny, nn);
        out_normals[wg * 3 + 2] = __fdiv_rn(nz, nn);
    }

    float ax = sx[0], ay = sy[0], bx = sx[1], by = sy[1], cx = sx[2], cy = sy[2];
    float d = (by - cy) * (ax - cx) + (cx - bx) * (ay - cy);
    float zmax = fmaxf(vz[0], fmaxf(vz[1], vz[2]));
    bool valid = (fabsf(d) > EPSF) && (zmax > EPSF);

    float dn = d + EPSF;
    float rd = __frcp_rn(dn);
    float4 A = make_float4(by - cy, cx - bx, cy - ay, ax - cx);
    float4 B = make_float4(cx, cy, rd, vz[0]);
    float4 Z = make_float4(vz[1], vz[2], 0.0f, 0.0f);

    if (lane == 0) {
        float4* F = reinterpret_cast<float4*>(g_face + wg * 12);
        F[0] = A; F[1] = B; F[2] = Z;
    }

    if (!valid) return;

    const float STEP = 2.0f / 127.0f;
    float pad = 1.0f * STEP;
    float xmin = fminf(ax, fminf(bx, cx)) - pad;
    float xmax = fmaxf(ax, fmaxf(bx, cx)) + pad;
    float ymin = fminf(ay, fminf(by, cy)) - pad;
    float ymax = fmaxf(ay, fmaxf(by, cy)) + pad;

    const float INV_STEP = 63.5f;       // 1 / (2/127)
    int x0 = max(0, (int)floorf((xmin + 1.0f) * INV_STEP));
    int x1 = min(IMG - 1, (int)ceilf((xmax + 1.0f) * INV_STEP));
    int y0 = max(0, (int)floorf((1.0f - ymax) * INV_STEP));
    int y1 = min(IMG - 1, (int)ceilf((1.0f - ymin) * INV_STEP));
    if (x0 > x1 || y0 > y1) return;

    unsigned long long* zb = g_zbuf + l * NPIX;
    unsigned fkey = 0xFFFFFFFFu - (unsigned)f;

    for (int y = y0; y <= y1; y++) {
        float py = pix_y(y);
        float dy = py - B.y;
        for (int x = x0 + lane; x <= x1; x += 32) {
            float px = pix_x(x);
            float dx = px - B.x;
            float l0 = (A.x * dx + A.y * dy) * B.z;
            float l1 = (A.z * dx + A.w * dy) * B.z;
            float l2 = 1.0f - l0 - l1;
            float z  = l0 * B.w + l1 * Z.x + l2 * Z.y;
            if (l0 >= 0.0f && l1 >= 0.0f && l2 >= 0.0f && z > EPSF) {
                unsigned long long key =
                    ((unsigned long long)(~__float_as_uint(z)) << 32) | fkey;
                atomicMax(&zb[y * IMG + x], key);
            }
        }
    }
}

// ---------------------------------------------------------------------------
// Kernel 2: shade. 192 threads / 64 pixels per block: 3 threads per pixel
// (one per layer) resolve winner -> barycentric -> uv -> texel coords, and
// RESET their zbuf entry to 0 (the empty state for the next graph replay);
// then 64 threads composite + fetch texture + write outputs.
// ---------------------------------------------------------------------------
__global__ void __launch_bounds__(192)
shade_kernel(const float* __restrict__ ts,
             const int*   __restrict__ faces,
             const float* __restrict__ uv,
             const float* __restrict__ tex,
             float* __restrict__ out) {
    __shared__ int s_tc[NB][64];        // packed (tyi<<16)|txi, -1 = miss
    int tid = threadIdx.x;
    int l = tid / 64;                   // layer for phase A
    int p = tid % 64;
    int pid = blockIdx.x * 64 + p;
    int x = pid & (IMG - 1), y = pid >> 7;
    float px = pix_x(x), py = pix_y(y);

    // ---- Phase A: per (layer, pixel) winner resolve + zbuf reset ----
    {
        unsigned long long key = g_zbuf[l * NPIX + pid];
        g_zbuf[l * NPIX + pid] = 0ull;          // restore empty state
        int packed = -1;
        if (key != 0ull) {
            int f = (int)(0xFFFFFFFFu - (unsigned)(key & 0xFFFFFFFFu));
            const float4* fd = reinterpret_cast<const float4*>(g_face + (l * NF + f) * 12);
            float4 A = fd[0];
            float4 B = fd[1];
            float dx = px - B.x, dy = py - B.y;
            float l0 = (A.x * dx + A.y * dy) * B.z;
            float l1 = (A.z * dx + A.w * dy) * B.z;
            float l2 = 1.0f - l0 - l1;
            int i0 = faces[f * 3 + 0];
            int i1 = faces[f * 3 + 1];
            int i2 = faces[f * 3 + 2];
            const float* U = uv + l * NP * 2;
            float u = l0 * U[2 * i0]     + l1 * U[2 * i1]     + l2 * U[2 * i2];
            float v = l0 * U[2 * i0 + 1] + l1 * U[2 * i1 + 1] + l2 * U[2 * i2 + 1];
            u = fminf(fmaxf(u, 0.0f), 1.0f);
            v = fminf(fmaxf(v, 0.0f), 1.0f);
            int txi = (int)rintf(u * 511.0f);
            int tyi = (int)rintf((1.0f - v) * 511.0f);
            packed = (tyi << 16) | txi;
        }
        s_tc[l][p] = packed;
    }
    __syncthreads();

    // ---- Phase B: composite + texture + write (threads 0..63) ----
    if (tid >= 64) return;

    // stable argsort of -ts[:,2]
    float k0 = -ts[2], k1 = -ts[5], k2 = -ts[8];
    int o0 = 0; float kv = k0;
    if (k1 < kv) { o0 = 1; kv = k1; }
    if (k2 < kv) { o0 = 2; kv = k2; }
    int r0i = (o0 == 0) ? 1 : 0;
    int r1i = (o0 == 2) ? 1 : 2;
    float kr0 = (r0i == 0) ? k0 : k1;
    float kr1 = (r1i == 1) ? k1 : k2;
    int o1, o2;
    if (kr0 <= kr1) { o1 = r0i; o2 = r1i; }
    else            { o1 = r1i; o2 = r0i; }

    int pc0 = s_tc[o0][p], pc1 = s_tc[o1][p], pc2 = s_tc[o2][p];
    int sel = o0, pc = pc0;
    if (pc1 >= 0) { sel = o1; pc = pc1; }
    if (pc2 >= 0) { sel = o2; pc = pc2; }

    float c0 = 0.0f, c1 = 0.0f, c2 = 0.0f, hard = 0.0f;
    if (pc >= 0) {
        hard = 1.0f;
        int txi = pc & 0xFFFF, tyi = pc >> 16;
        const float* T = tex + sel * 3 * 512 * 512 + tyi * 512 + txi;
        c0 = T[0];
        c1 = T[262144];
        c2 = T[524288];
    }

    out[OFF_IM + pid * 3 + 0] = c0;
    out[OFF_IM + pid * 3 + 1] = c1;
    out[OFF_IM + pid * 3 + 2] = c2;
    out[OFF_PROB + pid] = hard;
    out[OFF_FG + pid]   = hard;
}

// ---------------------------------------------------------------------------
extern "C" void kernel_launch(void* const* d_in, const int* in_sizes, int n_in,
                              void* d_out, int out_size) {
    const float* points = (const float*)d_in[0];
    const float* camrot = (const float*)d_in[1];
    const float* campos = (const float*)d_in[2];
    const float* proj   = (const float*)d_in[3];
    const float* uv     = (const float*)d_in[4];
    const float* tex    = (const float*)d_in[5];
    const float* ts     = (const float*)d_in[6];
    const int*   faces  = (const int*)d_in[7];
    float* out = (float*)d_out;

    scatter_kernel<<<(NB * NF * 32 + 255) / 256, 256>>>(points, camrot, campos,
                                                        proj, faces, out + OFF_NORM);
    shade_kernel<<<NPIX / 64, 192>>>(ts, faces, uv, tex, out);
}

// round 9
// speedup vs baseline: 70.0209x; 1.1148x over previous
#include <cuda_runtime.h>
#include <math.h>

#define EPSF 1e-8f
#define NB 3
#define NF 1024
#define NP 768
#define IMG 128
#define NPIX (IMG * IMG)

// out offsets (f32 elements)
#define OFF_IM     0
#define OFF_PROB   49152
#define OFF_NORM   65536
#define OFF_FG     74752

// Inverted-key z-buffer: 0 = empty (module-load default & post-shade state).
// key = (~bits(z))<<32 | (1023-f)<<18 | tyi<<9 | txi
//   atomicMax  =>  min z;  z-tie -> min face;  (tyi,txi) never affect order
//   because equal (z, f, pixel) implies equal texel coords.
static __device__ unsigned long long g_zbuf[NB * NPIX];

__device__ __forceinline__ float pix_x(int x) {
    const float STEP = 2.0f / 127.0f;
    return (x == 127) ? 1.0f : (-1.0f + x * STEP);
}
__device__ __forceinline__ float pix_y(int y) {
    const float STEP = 2.0f / 127.0f;
    return (y == 127) ? -1.0f : (1.0f - y * STEP);
}

// ---------------------------------------------------------------------------
// Kernel 1 (fused): per-(layer,face) prep + scatter rasterization with the
// full fragment payload (texel coords) packed into the atomicMax key.
// One warp per (layer, face).
// ---------------------------------------------------------------------------
__global__ void __launch_bounds__(256)
scatter_kernel(const float* __restrict__ pts,
               const float* __restrict__ camrot,
               const float* __restrict__ campos,
               const float* __restrict__ proj,
               const int*   __restrict__ faces,
               const float* __restrict__ uv,
               float* __restrict__ out_normals) {
    int wg = (blockIdx.x * blockDim.x + threadIdx.x) >> 5;
    int lane = threadIdx.x & 31;
    if (wg >= NB * NF) return;
    int l = wg >> 10;
    int f = wg & (NF - 1);

    int vis[3] = {faces[f * 3 + 0], faces[f * 3 + 1], faces[f * 3 + 2]};
    const float* R = camrot + l * 9;
    const float* C = campos + l * 3;
    float p0 = proj[0], p1 = proj[1];

    float vx[3], vy[3], vz[3], sx[3], sy[3];
#pragma unroll
    for (int k = 0; k < 3; k++) {
        const float* P = pts + (l * NP + vis[k]) * 3;
        float q0 = P[0] - C[0], q1 = P[1] - C[1], q2 = P[2] - C[2];
        float X = R[0] * q0 + R[1] * q1 + R[2] * q2;
        float Y = R[3] * q0 + R[4] * q1 + R[5] * q2;
        float Z = R[6] * q0 + R[7] * q1 + R[8] * q2;
        vx[k] = X; vy[k] = Y; vz[k] = Z;
        float zd = Z + EPSF;
        sx[k] = __fdiv_rn(X * p0, zd);
        sy[k] = __fdiv_rn(Y * p1, zd);
    }

    if (lane == 0) {
        float e1xx = vx[1] - vx[0], e1yy = vy[1] - vy[0], e1zz = vz[1] - vz[0];
        float e2xx = vx[2] - vx[0], e2yy = vy[2] - vy[0], e2zz = vz[2] - vz[0];
        float nx = e1yy * e2zz - e1zz * e2yy;
        float ny = e1zz * e2xx - e1xx * e2zz;
        float nz = e1xx * e2yy - e1yy * e2xx;
        float nn = __fsqrt_rn(nx * nx + ny * ny + nz * nz) + EPSF;
        out_normals[wg * 3 + 0] = __fdiv_rn(nx, nn);
        out_normals[wg * 3 + 1] = __fdiv_rn(ny, nn);
        out_normals[wg * 3 + 2] = __fdiv_rn(nz, nn);
    }

    float ax = sx[0], ay = sy[0], bx = sx[1], by = sy[1], cx = sx[2], cy = sy[2];
    float d = (by - cy) * (ax - cx) + (cx - bx) * (ay - cy);
    float zmax = fmaxf(vz[0], fmaxf(vz[1], vz[2]));
    bool valid = (fabsf(d) > EPSF) && (zmax > EPSF);
    if (!valid) return;

    float dn = d + EPSF;
    float rd = __frcp_rn(dn);
    float4 A = make_float4(by - cy, cx - bx, cy - ay, ax - cx);
    float4 B = make_float4(cx, cy, rd, vz[0]);
    float z1v = vz[1], z2v = vz[2];

    // per-face uv corners (identical values the old shade loaded)
    const float* U = uv + l * NP * 2;
    float u0 = U[2 * vis[0]],     u1 = U[2 * vis[1]],     u2 = U[2 * vis[2]];
    float v0 = U[2 * vis[0] + 1], v1 = U[2 * vis[1] + 1], v2 = U[2 * vis[2] + 1];

    const float STEP = 2.0f / 127.0f;
    float pad = 1.0f * STEP;
    float xmin = fminf(ax, fminf(bx, cx)) - pad;
    float xmax = fmaxf(ax, fmaxf(bx, cx)) + pad;
    float ymin = fminf(ay, fminf(by, cy)) - pad;
    float ymax = fmaxf(ay, fmaxf(by, cy)) + pad;

    const float INV_STEP = 63.5f;       // 1 / (2/127)
    int x0 = max(0, (int)floorf((xmin + 1.0f) * INV_STEP));
    int x1 = min(IMG - 1, (int)ceilf((xmax + 1.0f) * INV_STEP));
    int y0 = max(0, (int)floorf((1.0f - ymax) * INV_STEP));
    int y1 = min(IMG - 1, (int)ceilf((1.0f - ymin) * INV_STEP));
    if (x0 > x1 || y0 > y1) return;

    unsigned long long* zb = g_zbuf + l * NPIX;
    unsigned invf = 1023u - (unsigned)f;

    for (int y = y0; y <= y1; y++) {
        float py = pix_y(y);
        float dy = py - B.y;
        for (int x = x0 + lane; x <= x1; x += 32) {
            float px = pix_x(x);
            float dx = px - B.x;
            float l0 = (A.x * dx + A.y * dy) * B.z;
            float l1 = (A.z * dx + A.w * dy) * B.z;
            float l2 = 1.0f - l0 - l1;
            float z  = l0 * B.w + l1 * z1v + l2 * z2v;
            if (l0 >= 0.0f && l1 >= 0.0f && l2 >= 0.0f && z > EPSF) {
                // identical interpolation expressions as the previous shade
                float u = l0 * u0 + l1 * u1 + l2 * u2;
                float v = l0 * v0 + l1 * v1 + l2 * v2;
                u = fminf(fmaxf(u, 0.0f), 1.0f);
                v = fminf(fmaxf(v, 0.0f), 1.0f);
                unsigned txi = (unsigned)(int)rintf(u * 511.0f);
                unsigned tyi = (unsigned)(int)rintf((1.0f - v) * 511.0f);
                unsigned long long key =
                    ((unsigned long long)(~__float_as_uint(z)) << 32)
                    | (invf << 18) | (tyi << 9) | txi;
                atomicMax(&zb[y * IMG + x], key);
            }
        }
    }
}

// ---------------------------------------------------------------------------
// Kernel 2: shade. One thread per pixel. Chain: 3 zbuf loads (parallel) ->
// composite -> 3 texture loads (parallel) -> store. Resets zbuf to 0 (empty
// state for the next graph replay).
// ---------------------------------------------------------------------------
__global__ void __launch_bounds__(256)
shade_kernel(const float* __restrict__ ts,
             const float* __restrict__ tex,
             float* __restrict__ out) {
    int pid = blockIdx.x * blockDim.x + threadIdx.x;
    if (pid >= NPIX) return;

    unsigned long long k0v = g_zbuf[0 * NPIX + pid];
    unsigned long long k1v = g_zbuf[1 * NPIX + pid];
    unsigned long long k2v = g_zbuf[2 * NPIX + pid];
    g_zbuf[0 * NPIX + pid] = 0ull;
    g_zbuf[1 * NPIX + pid] = 0ull;
    g_zbuf[2 * NPIX + pid] = 0ull;
    unsigned long long keys[3] = {k0v, k1v, k2v};

    // stable argsort of -ts[:,2]
    float k0 = -ts[2], k1 = -ts[5], k2 = -ts[8];
    int o0 = 0; float kv = k0;
    if (k1 < kv) { o0 = 1; kv = k1; }
    if (k2 < kv) { o0 = 2; kv = k2; }
    int r0i = (o0 == 0) ? 1 : 0;
    int r1i = (o0 == 2) ? 1 : 2;
    float kr0 = (r0i == 0) ? k0 : k1;
    float kr1 = (r1i == 1) ? k1 : k2;
    int o1, o2;
    if (kr0 <= kr1) { o1 = r0i; o2 = r1i; }
    else            { o1 = r1i; o2 = r0i; }

    unsigned long long ksel = keys[o0];
    int sel = o0;
    if (keys[o1] != 0ull) { sel = o1; ksel = keys[o1]; }
    if (keys[o2] != 0ull) { sel = o2; ksel = keys[o2]; }

    float c0 = 0.0f, c1 = 0.0f, c2 = 0.0f, hard = 0.0f;
    if (ksel != 0ull) {
        hard = 1.0f;
        unsigned lo = (unsigned)(ksel & 0xFFFFFFFFull);
        int txi = lo & 511;
        int tyi = (lo >> 9) & 511;
        const float* T = tex + sel * 3 * 512 * 512 + tyi * 512 + txi;
        c0 = T[0];
        c1 = T[262144];
        c2 = T[524288];
    }

    out[OFF_IM + pid * 3 + 0] = c0;
    out[OFF_IM + pid * 3 + 1] = c1;
    out[OFF_IM + pid * 3 + 2] = c2;
    out[OFF_PROB + pid] = hard;
    out[OFF_FG + pid]   = hard;
}

// ---------------------------------------------------------------------------
extern "C" void kernel_launch(void* const* d_in, const int* in_sizes, int n_in,
                              void* d_out, int out_size) {
    const float* points = (const float*)d_in[0];
    const float* camrot = (const float*)d_in[1];
    const float* campos = (const float*)d_in[2];
    const float* proj   = (const float*)d_in[3];
    const float* uv     = (const float*)d_in[4];
    const float* tex    = (const float*)d_in[5];
    const float* ts     = (const float*)d_in[6];
    const int*   faces  = (const int*)d_in[7];
    float* out = (float*)d_out;

    scatter_kernel<<<(NB * NF * 32 + 255) / 256, 256>>>(points, camrot, campos,
                                                        proj, faces, uv,
                                                        out + OFF_NORM);
    shade_kernel<<<NPIX / 256, 256>>>(ts, tex, out);
}